// round 12
// baseline (speedup 1.0000x reference)
#include <cuda_runtime.h>
#include <cuda_bf16.h>
#include <math.h>

typedef unsigned long long ull;

#define N_TOT 262144
#define GS    64
#define NGRP  (N_TOT / GS)

#define PAD 68    // sxn / satt / sh stride (A-frag friendly)
#define SXS 66    // sx stride (float2-only access)
#define CHP 4096  // packed B chunk: 64k x 64col

// ---------------- device scratch (no allocations allowed) ----------------
__device__ ull   g_keys[2][N_TOT];
__device__ int   g_ind1[N_TOT];
__device__ int   g_ind2[N_TOT];
__device__ int   g_inv1[N_TOT];
__device__ int   g_ind12[N_TOT];
__device__ float g_x1[(size_t)N_TOT * 64];
// tf32 packed weights, 12 chunks per layer: 0-2 qkv, 3 wo, 4-7 ffa, 8-11 ffb
__device__ float g_wtf[2][12 * CHP];

// packed-B layout for m16n8k8: float4 at ((col>>3)*4 + (d>>4))*32 + (d&3)*8 + (col&7)
// holds d = {16*(d>>4)+ (d&3), +4, +8, +12} for col. Scalar index:
__device__ __forceinline__ int pb_idx(int d, int col)
{
    return ((col >> 3) * 4 + (d >> 4)) * 128 + (d & 3) * 32 + (col & 7) * 4
         + 2 * ((d >> 3) & 1) + ((d >> 2) & 1);
}

// ---------------- Hilbert encode (Skilling), order = 10 ----------------
__device__ __forceinline__ unsigned hilbert3(unsigned X0, unsigned X1, unsigned X2)
{
    const int order = 10;
    for (unsigned Q = 1u << (order - 1); Q > 1; Q >>= 1) {
        unsigned P = Q - 1;
        if (X0 & Q) X0 ^= P;
        unsigned t = (X0 ^ X1) & P;
        if (X1 & Q) { X0 ^= P; } else { X0 ^= t; X1 ^= t; }
        t = (X0 ^ X2) & P;
        if (X2 & Q) { X0 ^= P; } else { X0 ^= t; X2 ^= t; }
    }
    X1 ^= X0;
    X2 ^= X1;
    unsigned t = 0;
    for (unsigned Q = 1u << (order - 1); Q > 1; Q >>= 1)
        if (X2 & Q) t ^= (Q - 1);
    X0 ^= t; X1 ^= t; X2 ^= t;
    unsigned code = 0;
#pragma unroll
    for (int b = order - 1; b >= 0; b--) {
        code = (code << 3) | (((X0 >> b) & 1u) << 2) | (((X1 >> b) & 1u) << 1) | ((X2 >> b) & 1u);
    }
    return code;
}

__global__ void __launch_bounds__(256) codes_kernel(const int* __restrict__ vox_coors)
{
    int i = blockIdx.x * 256 + threadIdx.x;
    if (i >= N_TOT) return;
    int4 v = ((const int4*)vox_coors)[i];
    unsigned b  = (unsigned)v.x;
    unsigned c1 = hilbert3((unsigned)v.y, (unsigned)v.z,      (unsigned)v.w);
    unsigned c2 = hilbert3((unsigned)v.y, (unsigned)v.z + 1u, (unsigned)v.w + 1u);
    // Reference keys are int32 (JAX x64 off): batch<<30 overflows the sign bit;
    // signed ascending == unsigned ascending of (key ^ 0x80000000).
    unsigned k1 = (((b << 30) | c1) ^ 0x80000000u);
    unsigned k2 = (((b << 30) | c2) ^ 0x80000000u);
    g_keys[0][i] = (((ull)k1) << 32) | (unsigned)i;
    g_keys[1][i] = (((ull)k2) << 32) | (unsigned)i;
}

// ---------------- bitonic sort (uint64 ascending, N = 2^18) ----------------
__global__ void __launch_bounds__(1024) bitonic_local_sort()
{
    __shared__ ull s[4096];
    ull* arr = g_keys[blockIdx.y];
    int base = blockIdx.x * 4096;
    int tid = threadIdx.x;
#pragma unroll
    for (int e = 0; e < 4; e++) s[e * 1024 + tid] = arr[base + e * 1024 + tid];
    __syncthreads();
    for (int k = 2; k <= 4096; k <<= 1) {
        for (int j = k >> 1; j >= 1; j >>= 1) {
#pragma unroll
            for (int e = 0; e < 2; e++) {
                int v = e * 1024 + tid;
                int i = ((v & ~(j - 1)) << 1) | (v & (j - 1));
                int l = i | j;
                bool up = (((unsigned)(base + i)) & (unsigned)k) == 0;
                ull A = s[i], B = s[l];
                if ((A > B) == up) { s[i] = B; s[l] = A; }
            }
            __syncthreads();
        }
    }
#pragma unroll
    for (int e = 0; e < 4; e++) arr[base + e * 1024 + tid] = s[e * 1024 + tid];
}

__global__ void __launch_bounds__(1024) bitonic_local_merge(int k)
{
    __shared__ ull s[4096];
    ull* arr = g_keys[blockIdx.y];
    int base = blockIdx.x * 4096;
    int tid = threadIdx.x;
#pragma unroll
    for (int e = 0; e < 4; e++) s[e * 1024 + tid] = arr[base + e * 1024 + tid];
    __syncthreads();
    bool up = (((unsigned)base) & (unsigned)k) == 0;
    for (int j = 2048; j >= 1; j >>= 1) {
#pragma unroll
        for (int e = 0; e < 2; e++) {
            int v = e * 1024 + tid;
            int i = ((v & ~(j - 1)) << 1) | (v & (j - 1));
            int l = i | j;
            ull A = s[i], B = s[l];
            if ((A > B) == up) { s[i] = B; s[l] = A; }
        }
        __syncthreads();
    }
#pragma unroll
    for (int e = 0; e < 4; e++) arr[base + e * 1024 + tid] = s[e * 1024 + tid];
}

__global__ void __launch_bounds__(256) bitonic_global(int k, int j)
{
    ull* arr = g_keys[blockIdx.y];
    int v = blockIdx.x * 256 + threadIdx.x;
    int i = ((v & ~(j - 1)) << 1) | (v & (j - 1));
    int l = i | j;
    bool up = (((unsigned)i) & (unsigned)k) == 0;
    ull A = arr[i], B = arr[l];
    if ((A > B) == up) { arr[i] = B; arr[l] = A; }
}

// fused pair of global steps (j, then j/2), j >= 8192. Quartet spacing m=j/2;
// direction uniform within a quartet since k >= 2j = 4m.
__global__ void __launch_bounds__(256) bitonic_global2(int k, int j)
{
    ull* arr = g_keys[blockIdx.y];
    int m = j >> 1;
    int v = blockIdx.x * 256 + threadIdx.x;          // 0 .. N/4-1
    int i0 = ((v & ~(m - 1)) << 2) | (v & (m - 1));
    bool up = (((unsigned)i0) & (unsigned)k) == 0;
    ull e0 = arr[i0], e1 = arr[i0 + m], e2 = arr[i0 + 2 * m], e3 = arr[i0 + 3 * m];
    if ((e0 > e2) == up) { ull t = e0; e0 = e2; e2 = t; }
    if ((e1 > e3) == up) { ull t = e1; e1 = e3; e3 = t; }
    if ((e0 > e1) == up) { ull t = e0; e0 = e1; e1 = t; }
    if ((e2 > e3) == up) { ull t = e2; e2 = e3; e3 = t; }
    arr[i0] = e0; arr[i0 + m] = e1; arr[i0 + 2 * m] = e2; arr[i0 + 3 * m] = e3;
}

__global__ void __launch_bounds__(256) extract_kernel()
{
    int i = blockIdx.x * 256 + threadIdx.x;
    int i1 = (int)(g_keys[0][i] & 0xffffffffull);
    int i2 = (int)(g_keys[1][i] & 0xffffffffull);
    g_ind1[i] = i1;
    g_ind2[i] = i2;
    g_inv1[i1] = i;
}

__global__ void __launch_bounds__(256) ind12_kernel()
{
    int i = blockIdx.x * 256 + threadIdx.x;
    g_ind12[i] = g_inv1[g_ind2[i]];
}

// ---------------- tf32 helpers ----------------
__device__ __forceinline__ float tf32r(float x)
{
    unsigned u;
    asm("cvt.rna.tf32.f32 %0, %1;" : "=r"(u) : "f"(x));
    return __uint_as_float(u);
}

// weight pre-convert into packed-B tf32 chunks
__global__ void __launch_bounds__(256) wconv_kernel(
    int layer,
    const float* __restrict__ wqkv, const float* __restrict__ wo,
    const float* __restrict__ wffa, const float* __restrict__ wffb)
{
    int idx = blockIdx.x * 256 + threadIdx.x;
    if (idx >= 12 * CHP) return;
    int cid = idx >> 12;
    int rem = idx & 4095;
    int r = rem >> 6, n = rem & 63;
    float v;
    if (cid < 3)       v = wqkv[r * 192 + 64 * cid + n];
    else if (cid == 3) v = wo[r * 64 + n];
    else if (cid < 8)  v = wffa[r * 256 + 64 * (cid - 4) + n];
    else               v = wffb[(64 * (cid - 8) + r) * 64 + n];
    g_wtf[layer][cid * CHP + pb_idx(r, n)] = tf32r(v);
}

// m16n8k8 tf32 mma. A: a0=(g,t) a1=(g+8,t) a2=(g,t+4) a3=(g+8,t+4);
// B: b0=(k t, col g) b1=(k t+4, col g); D as k4. (g=lane>>2, t=lane&3)
__device__ __forceinline__ void mma8(float4& d, const float* a, float b0, float b1)
{
    asm volatile("mma.sync.aligned.m16n8k8.row.col.f32.tf32.tf32.f32 "
                 "{%0,%1,%2,%3}, {%4,%5,%6,%7}, {%8,%9}, {%0,%1,%2,%3};"
                 : "+f"(d.x), "+f"(d.y), "+f"(d.z), "+f"(d.w)
                 : "r"(__float_as_uint(a[0])), "r"(__float_as_uint(a[1])),
                   "r"(__float_as_uint(a[2])), "r"(__float_as_uint(a[3])),
                   "r"(__float_as_uint(b0)), "r"(__float_as_uint(b1)));
}

// A-fragments for K=64 (8 k8-steps)
__device__ __forceinline__ void load_afrag8(const float* A, int stride, int mrow,
                                            int gid, int tig, float a[8][4])
{
#pragma unroll
    for (int j = 0; j < 8; j++) {
        a[j][0] = A[(mrow + gid) * stride + 8 * j + tig];
        a[j][1] = A[(mrow + gid + 8) * stride + 8 * j + tig];
        a[j][2] = A[(mrow + gid) * stride + 8 * j + tig + 4];
        a[j][3] = A[(mrow + gid + 8) * stride + 8 * j + tig + 4];
    }
}

// 64-K GEMM vs packed-B chunk, one 8-col block cb
__device__ __forceinline__ void gemm64(const float a[8][4], const float* pb,
                                       int cb, int tig, int gid, float4& acc)
{
    const float4* pb4 = (const float4*)pb;
#pragma unroll
    for (int j2 = 0; j2 < 4; j2++) {
        float4 b = pb4[(cb * 4 + j2) * 32 + tig * 8 + gid];
        mma8(acc, a[2 * j2],     b.x, b.y);
        mma8(acc, a[2 * j2 + 1], b.z, b.w);
    }
}

__device__ __forceinline__ float gelu_tanh(float x)
{
    float x3 = x * x * x;
    float t = tanhf(0.7978845608028654f * (x + 0.044715f * x3));
    return 0.5f * x * (1.0f + t);
}

// layernorm rows: sx[64][SXS] -> tf32 sxn[64][PAD]  (8 warps x 8 rows)
__device__ __forceinline__ void ln_rows(const float* sx, float* sxn, int tid)
{
    int lane = tid & 31, w = tid >> 5;
#pragma unroll
    for (int rr = 0; rr < 8; rr++) {
        int r = w * 8 + rr;
        float a = sx[r * SXS + lane];
        float b = sx[r * SXS + lane + 32];
        float s = a + b, q = a * a + b * b;
#pragma unroll
        for (int m = 16; m; m >>= 1) {
            s += __shfl_xor_sync(0xffffffffu, s, m);
            q += __shfl_xor_sync(0xffffffffu, q, m);
        }
        float mean = s * (1.0f / 64.0f);
        float rs = rsqrtf(q * (1.0f / 64.0f) - mean * mean + 1e-5f);
        sxn[r * PAD + lane]      = tf32r((a - mean) * rs);
        sxn[r * PAD + lane + 32] = tf32r((b - mean) * rs);
    }
}

// smem: sx 64*66 | sxn 64*68 | pkT 4096 | pv 4096 | satt 128*68
#define SMEM_FLOATS (64*SXS + 64*PAD + CHP + CHP + 128*PAD)
#define SMEM_BYTES  (SMEM_FLOATS * 4)   // 101888 B -> 2 blocks/SM

__global__ void __launch_bounds__(256, 2) layer_kernel(
    int layer,
    const float* __restrict__ feats_in, const float* __restrict__ pts,
    const float* __restrict__ wpos, float* __restrict__ dst_out)
{
    extern __shared__ float smf[];
    float* sx   = smf;                  // [64][66] fp32 residual
    float* sxn  = sx   + 64 * SXS;      // [64][68] ln-out / q / o / ln2 (A-layout)
    float* pkT  = sxn  + 64 * PAD;      // packed B: k (d=dim, col=key) / ffa weights
    float* pv   = pkT  + CHP;           // packed B: v (d=key, col=vd) / ffb weights
    float* satt = pv   + CHP;           // [128][68] att / weight staging / sh
    float* sh   = satt;

    const float* wtf   = g_wtf[layer];
    const float* feats = layer ? g_x1   : feats_in;
    float*       dst   = layer ? dst_out : g_x1;
    const int*   gIdx  = layer ? g_ind12 : g_ind1;
    const int*   pIdx  = layer ? g_ind2  : g_ind1;

    int tid = threadIdx.x;
    int g = blockIdx.x;
    int lane = tid & 31, w = tid >> 5;
    int gid = lane >> 2, tig = lane & 3;
    int mrow = 16 * (w & 3), wsel = w >> 2;   // GEMM map: 4 M-tiles x 2 col-phases
    int hh2 = w & 1, mr2 = 16 * (w >> 1);     // attention map: 2 heads x 4 M-tiles

    float a[8][4];

    // ---- P0: stage wpos (satt); x = feats[gIdx] + p @ wpos ----
    satt[tid] = wpos[tid];
    __syncthreads();
    {
        int r = tid >> 2;
        int cs = (tid & 3) * 16;
        int gi = gIdx[g * GS + r];
        int pi = pIdx[g * GS + r];
        float4 p = *(const float4*)(pts + (size_t)pi * 4);
#pragma unroll
        for (int cc = 0; cc < 16; cc += 4) {
            int c = cs + cc;
            float4 f  = *(const float4*)(feats + (size_t)gi * 64 + c);
            float4 w0 = *(const float4*)(satt + c);
            float4 w1 = *(const float4*)(satt + 64 + c);
            float4 w2 = *(const float4*)(satt + 128 + c);
            float4 w3 = *(const float4*)(satt + 192 + c);
            f.x += p.x * w0.x + p.y * w1.x + p.z * w2.x + p.w * w3.x;
            f.y += p.x * w0.y + p.y * w1.y + p.z * w2.y + p.w * w3.y;
            f.z += p.x * w0.z + p.y * w1.z + p.z * w2.z + p.w * w3.z;
            f.w += p.x * w0.w + p.y * w1.w + p.z * w2.w + p.w * w3.w;
            *(float2*)(sx + r * SXS + c)     = make_float2(f.x, f.y);
            *(float2*)(sx + r * SXS + c + 2) = make_float2(f.z, f.w);
        }
    }
    __syncthreads();

    // ---- P1: ln -> sxn ----
    ln_rows(sx, sxn, tid);
    __syncthreads();

    // ---- P2: q/k/v GEMMs ----
    load_afrag8(sxn, PAD, mrow, gid, tig, a);   // ln frags persist across s
#pragma unroll 1
    for (int s = 0; s < 3; s++) {
        const float4* ws = (const float4*)(wtf + s * CHP);
        for (int i = tid; i < 1024; i += 256) ((float4*)satt)[i] = ws[i];
        __syncthreads();
        float4 acc[4];
#pragma unroll
        for (int u = 0; u < 4; u++) {
            acc[u] = make_float4(0.f, 0.f, 0.f, 0.f);
            gemm64(a, satt, wsel + 2 * u, tig, gid, acc[u]);
        }
#pragma unroll
        for (int u = 0; u < 4; u++) {
            int n0 = 8 * (wsel + 2 * u) + 2 * tig, r0 = mrow + gid;
            if (s == 0) {          // q row-major into sxn
                sxn[r0 * PAD + n0]           = tf32r(acc[u].x);
                sxn[r0 * PAD + n0 + 1]       = tf32r(acc[u].y);
                sxn[(r0 + 8) * PAD + n0]     = tf32r(acc[u].z);
                sxn[(r0 + 8) * PAD + n0 + 1] = tf32r(acc[u].w);
            } else if (s == 1) {   // k packed: d=dim(n0), col=key(r0)
                pkT[pb_idx(n0, r0)]         = tf32r(acc[u].x);
                pkT[pb_idx(n0 + 1, r0)]     = tf32r(acc[u].y);
                pkT[pb_idx(n0, r0 + 8)]     = tf32r(acc[u].z);
                pkT[pb_idx(n0 + 1, r0 + 8)] = tf32r(acc[u].w);
            } else {               // v packed: d=key(r0), col=vd(n0)
                pv[pb_idx(r0, n0)]          = tf32r(acc[u].x);
                pv[pb_idx(r0, n0 + 1)]      = tf32r(acc[u].y);
                pv[pb_idx(r0 + 8, n0)]      = tf32r(acc[u].z);
                pv[pb_idx(r0 + 8, n0 + 1)]  = tf32r(acc[u].w);
            }
        }
        __syncthreads();
    }

    // ---- P3: attention (scores + in-register softmax, then AV) ----
#pragma unroll 1
    for (int p = 0; p < 2; p++) {
        int h = 2 * p + hh2;
        float qa[2][4];
#pragma unroll
        for (int j = 0; j < 2; j++) {
            qa[j][0] = sxn[(mr2 + gid) * PAD + 16 * h + 8 * j + tig];
            qa[j][1] = sxn[(mr2 + gid + 8) * PAD + 16 * h + 8 * j + tig];
            qa[j][2] = sxn[(mr2 + gid) * PAD + 16 * h + 8 * j + tig + 4];
            qa[j][3] = sxn[(mr2 + gid + 8) * PAD + 16 * h + 8 * j + tig + 4];
        }
        float4 sc[8];
        const float4* pk4 = (const float4*)pkT;
#pragma unroll
        for (int u = 0; u < 8; u++) {
            sc[u] = make_float4(0.f, 0.f, 0.f, 0.f);
            float4 b = pk4[(u * 4 + h) * 32 + tig * 8 + gid];  // d-block j2=h
            mma8(sc[u], qa[0], b.x, b.y);
            mma8(sc[u], qa[1], b.z, b.w);
        }
        float s0 = 0.0f, s1 = 0.0f;
#pragma unroll
        for (int u = 0; u < 8; u++) {
            sc[u].x = __expf(sc[u].x * 0.25f);  // 1/sqrt(16); scores O(1), no max
            sc[u].y = __expf(sc[u].y * 0.25f);
            sc[u].z = __expf(sc[u].z * 0.25f);
            sc[u].w = __expf(sc[u].w * 0.25f);
            s0 += sc[u].x + sc[u].y;
            s1 += sc[u].z + sc[u].w;
        }
        s0 += __shfl_xor_sync(0xffffffffu, s0, 1);
        s0 += __shfl_xor_sync(0xffffffffu, s0, 2);
        s1 += __shfl_xor_sync(0xffffffffu, s1, 1);
        s1 += __shfl_xor_sync(0xffffffffu, s1, 2);
        float i0 = 1.0f / s0, i1 = 1.0f / s1;
        int ar = hh2 * 64 + mr2 + gid;
#pragma unroll
        for (int u = 0; u < 8; u++) {
            int n0 = 8 * u + 2 * tig;
            satt[ar * PAD + n0]           = tf32r(sc[u].x * i0);
            satt[ar * PAD + n0 + 1]       = tf32r(sc[u].y * i0);
            satt[(ar + 8) * PAD + n0]     = tf32r(sc[u].z * i1);
            satt[(ar + 8) * PAD + n0 + 1] = tf32r(sc[u].w * i1);
        }
        __syncthreads();
        // AV: o = att @ v -> sxn cols [16h, 16h+16)
        load_afrag8(satt + hh2 * 64 * PAD, PAD, mr2, gid, tig, a);
#pragma unroll
        for (int u = 0; u < 2; u++) {
            float4 acc = make_float4(0.f, 0.f, 0.f, 0.f);
            gemm64(a, pv, 2 * h + u, tig, gid, acc);
            int r0 = mr2 + gid, n0 = 16 * h + 8 * u + 2 * tig;
            sxn[r0 * PAD + n0]           = tf32r(acc.x);
            sxn[r0 * PAD + n0 + 1]       = tf32r(acc.y);
            sxn[(r0 + 8) * PAD + n0]     = tf32r(acc.z);
            sxn[(r0 + 8) * PAD + n0 + 1] = tf32r(acc.w);
        }
        __syncthreads();
    }

    // ---- P3c: x += o @ wo; pre-stage ffa0 (pkT) + ffb0 (pv) ----
    load_afrag8(sxn, PAD, mrow, gid, tig, a);   // o frags
    {
        const float4* wo4 = (const float4*)(wtf + 3 * CHP);
        const float4* fa4 = (const float4*)(wtf + 4 * CHP);
        const float4* fb4 = (const float4*)(wtf + 8 * CHP);
        for (int i = tid; i < 1024; i += 256) {
            ((float4*)satt)[i] = wo4[i];
            ((float4*)pkT)[i]  = fa4[i];
            ((float4*)pv)[i]   = fb4[i];
        }
    }
    __syncthreads();
    {
        float4 acc[4];
#pragma unroll
        for (int u = 0; u < 4; u++) {
            acc[u] = make_float4(0.f, 0.f, 0.f, 0.f);
            gemm64(a, satt, wsel + 2 * u, tig, gid, acc[u]);
        }
#pragma unroll
        for (int u = 0; u < 4; u++) {
            int n0 = 8 * (wsel + 2 * u) + 2 * tig, r0 = mrow + gid;
            sx[r0 * SXS + n0]           += acc[u].x;
            sx[r0 * SXS + n0 + 1]       += acc[u].y;
            sx[(r0 + 8) * SXS + n0]     += acc[u].z;
            sx[(r0 + 8) * SXS + n0 + 1] += acc[u].w;
        }
    }
    __syncthreads();

    // ---- P4: FF, 4 quarters, 2-phase pipeline ----
    ln_rows(sx, sxn, tid);
    __syncthreads();
    float4 accB[4];
#pragma unroll
    for (int u = 0; u < 4; u++) accB[u] = make_float4(0.f, 0.f, 0.f, 0.f);

#pragma unroll 1
    for (int qtr = 0; qtr < 4; qtr++) {
        // phase A: stage ffb(qtr) [qtr>0] || ffa mma -> gelu -> sh
        if (qtr > 0) {
            const float4* fb4 = (const float4*)(wtf + (8 + qtr) * CHP);
            for (int i = tid; i < 1024; i += 256) ((float4*)pv)[i] = fb4[i];
        }
        load_afrag8(sxn, PAD, mrow, gid, tig, a);
        float4 acc[4];
#pragma unroll
        for (int u = 0; u < 4; u++) {
            acc[u] = make_float4(0.f, 0.f, 0.f, 0.f);
            gemm64(a, pkT, wsel + 2 * u, tig, gid, acc[u]);
        }
#pragma unroll
        for (int u = 0; u < 4; u++) {
            int n0 = 8 * (wsel + 2 * u) + 2 * tig, r0 = mrow + gid;
            sh[r0 * PAD + n0]           = tf32r(gelu_tanh(acc[u].x));
            sh[r0 * PAD + n0 + 1]       = tf32r(gelu_tanh(acc[u].y));
            sh[(r0 + 8) * PAD + n0]     = tf32r(gelu_tanh(acc[u].z));
            sh[(r0 + 8) * PAD + n0 + 1] = tf32r(gelu_tanh(acc[u].w));
        }
        __syncthreads();
        // phase B: stage ffa(qtr+1) [qtr<3] || ffb mma -> accB
        if (qtr < 3) {
            const float4* fa4 = (const float4*)(wtf + (4 + qtr + 1) * CHP);
            for (int i = tid; i < 1024; i += 256) ((float4*)pkT)[i] = fa4[i];
        }
        load_afrag8(sh, PAD, mrow, gid, tig, a);
#pragma unroll
        for (int u = 0; u < 4; u++)
            gemm64(a, pv, wsel + 2 * u, tig, gid, accB[u]);
        __syncthreads();
    }

    // ---- write out: dst = x + ff ----
#pragma unroll
    for (int u = 0; u < 4; u++) {
        int n0 = 8 * (wsel + 2 * u) + 2 * tig, r0 = mrow + gid;
        float2 lo = make_float2(sx[r0 * SXS + n0] + accB[u].x,
                                sx[r0 * SXS + n0 + 1] + accB[u].y);
        float2 hi = make_float2(sx[(r0 + 8) * SXS + n0] + accB[u].z,
                                sx[(r0 + 8) * SXS + n0 + 1] + accB[u].w);
        *(float2*)(dst + (size_t)(g * GS + r0) * 64 + n0)     = lo;
        *(float2*)(dst + (size_t)(g * GS + r0 + 8) * 64 + n0) = hi;
    }
}

// ---------------- launch ----------------
extern "C" void kernel_launch(void* const* d_in, const int* in_sizes, int n_in,
                              void* d_out, int out_size)
{
    const float* vox_feats = (const float*)d_in[0];
    const float* pts_coors = (const float*)d_in[1];
    const int*   vox_coors = (const int*)d_in[2];
    const float* w[10];
    for (int i = 0; i < 10; i++) w[i] = (const float*)d_in[n_in - 10 + i];
    float* out = (float*)d_out;

    cudaFuncSetAttribute(layer_kernel, cudaFuncAttributeMaxDynamicSharedMemorySize, SMEM_BYTES);

    codes_kernel<<<N_TOT / 256, 256>>>(vox_coors);
    wconv_kernel<<<(12 * CHP + 255) / 256, 256>>>(0, w[1], w[2], w[3], w[4]);
    wconv_kernel<<<(12 * CHP + 255) / 256, 256>>>(1, w[6], w[7], w[8], w[9]);

    dim3 gl(64, 2);
    bitonic_local_sort<<<gl, 1024>>>();
    for (int k = 8192; k <= N_TOT; k <<= 1) {
        int j = k >> 1;
        while (j >= 4096) {
            if (j >= 8192) {
                bitonic_global2<<<dim3(256, 2), 256>>>(k, j);
                j >>= 2;
            } else {
                bitonic_global<<<dim3(512, 2), 256>>>(k, j);
                j >>= 1;
            }
        }
        bitonic_local_merge<<<gl, 1024>>>(k);
    }

    extract_kernel<<<N_TOT / 256, 256>>>();
    ind12_kernel<<<N_TOT / 256, 256>>>();

    layer_kernel<<<NGRP, 256, SMEM_BYTES>>>(0, vox_feats, pts_coors, w[0], out);
    layer_kernel<<<NGRP, 256, SMEM_BYTES>>>(1, vox_feats, pts_coors, w[5], out);
}

// round 14
// speedup vs baseline: 1.5046x; 1.5046x over previous
#include <cuda_runtime.h>
#include <cuda_bf16.h>
#include <math.h>

typedef unsigned long long ull;

#define N_TOT 262144
#define GS    64
#define NGRP  (N_TOT / GS)

#define PAD 68    // sxn / satt / sh stride (A-frag friendly)
#define SXS 66    // sx stride (float2-only access)
#define CHP 4096  // packed B chunk: 64k x 64col

// ---------------- device scratch (no allocations allowed) ----------------
__device__ ull   g_keys[2][N_TOT];
__device__ int   g_ind1[N_TOT];
__device__ int   g_ind2[N_TOT];
__device__ int   g_inv1[N_TOT];
__device__ int   g_ind12[N_TOT];
__device__ float g_x1[(size_t)N_TOT * 64];
// tf32 packed weights, 12 chunks per layer: 0-2 qkv, 3 wo, 4-7 ffa, 8-11 ffb
__device__ float g_wtf[2][12 * CHP];

// packed-B layout for m16n8k8, CONFLICT-FREE: within block ((col>>3)*4 + (d>>4)),
// the float4 for (col, d-quad) sits at float4-index ((col&7)*4 + (d&3)) == lane id
// of the consumer thread (gid=col&7, tig=d&3) -> each 8-lane LDS.128 phase reads
// 128 contiguous bytes. float4 components = d offsets {0,+4,+8,+12}.
__device__ __forceinline__ int pb_idx(int d, int col)
{
    return ((col >> 3) * 4 + (d >> 4)) * 128 + ((col & 7) * 4 + (d & 3)) * 4
         + 2 * ((d >> 3) & 1) + ((d >> 2) & 1);
}

// ---------------- Hilbert encode (Skilling), order = 10 ----------------
__device__ __forceinline__ unsigned hilbert3(unsigned X0, unsigned X1, unsigned X2)
{
    const int order = 10;
    for (unsigned Q = 1u << (order - 1); Q > 1; Q >>= 1) {
        unsigned P = Q - 1;
        if (X0 & Q) X0 ^= P;
        unsigned t = (X0 ^ X1) & P;
        if (X1 & Q) { X0 ^= P; } else { X0 ^= t; X1 ^= t; }
        t = (X0 ^ X2) & P;
        if (X2 & Q) { X0 ^= P; } else { X0 ^= t; X2 ^= t; }
    }
    X1 ^= X0;
    X2 ^= X1;
    unsigned t = 0;
    for (unsigned Q = 1u << (order - 1); Q > 1; Q >>= 1)
        if (X2 & Q) t ^= (Q - 1);
    X0 ^= t; X1 ^= t; X2 ^= t;
    unsigned code = 0;
#pragma unroll
    for (int b = order - 1; b >= 0; b--) {
        code = (code << 3) | (((X0 >> b) & 1u) << 2) | (((X1 >> b) & 1u) << 1) | ((X2 >> b) & 1u);
    }
    return code;
}

__global__ void __launch_bounds__(256) codes_kernel(const int* __restrict__ vox_coors)
{
    int i = blockIdx.x * 256 + threadIdx.x;
    if (i >= N_TOT) return;
    int4 v = ((const int4*)vox_coors)[i];
    unsigned b  = (unsigned)v.x;
    unsigned c1 = hilbert3((unsigned)v.y, (unsigned)v.z,      (unsigned)v.w);
    unsigned c2 = hilbert3((unsigned)v.y, (unsigned)v.z + 1u, (unsigned)v.w + 1u);
    // Reference keys are int32 (JAX x64 off): batch<<30 overflows the sign bit;
    // signed ascending == unsigned ascending of (key ^ 0x80000000).
    unsigned k1 = (((b << 30) | c1) ^ 0x80000000u);
    unsigned k2 = (((b << 30) | c2) ^ 0x80000000u);
    g_keys[0][i] = (((ull)k1) << 32) | (unsigned)i;
    g_keys[1][i] = (((ull)k2) << 32) | (unsigned)i;
}

// ---------------- bitonic sort (uint64 ascending, N = 2^18) ----------------
__global__ void __launch_bounds__(1024) bitonic_local_sort()
{
    __shared__ ull s[4096];
    ull* arr = g_keys[blockIdx.y];
    int base = blockIdx.x * 4096;
    int tid = threadIdx.x;
#pragma unroll
    for (int e = 0; e < 4; e++) s[e * 1024 + tid] = arr[base + e * 1024 + tid];
    __syncthreads();
    for (int k = 2; k <= 4096; k <<= 1) {
        for (int j = k >> 1; j >= 1; j >>= 1) {
#pragma unroll
            for (int e = 0; e < 2; e++) {
                int v = e * 1024 + tid;
                int i = ((v & ~(j - 1)) << 1) | (v & (j - 1));
                int l = i | j;
                bool up = (((unsigned)(base + i)) & (unsigned)k) == 0;
                ull A = s[i], B = s[l];
                if ((A > B) == up) { s[i] = B; s[l] = A; }
            }
            __syncthreads();
        }
    }
#pragma unroll
    for (int e = 0; e < 4; e++) arr[base + e * 1024 + tid] = s[e * 1024 + tid];
}

__global__ void __launch_bounds__(1024) bitonic_local_merge(int k)
{
    __shared__ ull s[4096];
    ull* arr = g_keys[blockIdx.y];
    int base = blockIdx.x * 4096;
    int tid = threadIdx.x;
#pragma unroll
    for (int e = 0; e < 4; e++) s[e * 1024 + tid] = arr[base + e * 1024 + tid];
    __syncthreads();
    bool up = (((unsigned)base) & (unsigned)k) == 0;
    for (int j = 2048; j >= 1; j >>= 1) {
#pragma unroll
        for (int e = 0; e < 2; e++) {
            int v = e * 1024 + tid;
            int i = ((v & ~(j - 1)) << 1) | (v & (j - 1));
            int l = i | j;
            ull A = s[i], B = s[l];
            if ((A > B) == up) { s[i] = B; s[l] = A; }
        }
        __syncthreads();
    }
#pragma unroll
    for (int e = 0; e < 4; e++) arr[base + e * 1024 + tid] = s[e * 1024 + tid];
}

__global__ void __launch_bounds__(256) bitonic_global(int k, int j)
{
    ull* arr = g_keys[blockIdx.y];
    int v = blockIdx.x * 256 + threadIdx.x;
    int i = ((v & ~(j - 1)) << 1) | (v & (j - 1));
    int l = i | j;
    bool up = (((unsigned)i) & (unsigned)k) == 0;
    ull A = arr[i], B = arr[l];
    if ((A > B) == up) { arr[i] = B; arr[l] = A; }
}

// fused pair of global steps (j, then j/2), j >= 8192. Quartet spacing m=j/2;
// direction uniform within a quartet since k >= 2j = 4m.
__global__ void __launch_bounds__(256) bitonic_global2(int k, int j)
{
    ull* arr = g_keys[blockIdx.y];
    int m = j >> 1;
    int v = blockIdx.x * 256 + threadIdx.x;          // 0 .. N/4-1
    int i0 = ((v & ~(m - 1)) << 2) | (v & (m - 1));
    bool up = (((unsigned)i0) & (unsigned)k) == 0;
    ull e0 = arr[i0], e1 = arr[i0 + m], e2 = arr[i0 + 2 * m], e3 = arr[i0 + 3 * m];
    if ((e0 > e2) == up) { ull t = e0; e0 = e2; e2 = t; }
    if ((e1 > e3) == up) { ull t = e1; e1 = e3; e3 = t; }
    if ((e0 > e1) == up) { ull t = e0; e0 = e1; e1 = t; }
    if ((e2 > e3) == up) { ull t = e2; e2 = e3; e3 = t; }
    arr[i0] = e0; arr[i0 + m] = e1; arr[i0 + 2 * m] = e2; arr[i0 + 3 * m] = e3;
}

__global__ void __launch_bounds__(256) extract_kernel()
{
    int i = blockIdx.x * 256 + threadIdx.x;
    int i1 = (int)(g_keys[0][i] & 0xffffffffull);
    int i2 = (int)(g_keys[1][i] & 0xffffffffull);
    g_ind1[i] = i1;
    g_ind2[i] = i2;
    g_inv1[i1] = i;
}

__global__ void __launch_bounds__(256) ind12_kernel()
{
    int i = blockIdx.x * 256 + threadIdx.x;
    g_ind12[i] = g_inv1[g_ind2[i]];
}

// ---------------- tf32 helpers ----------------
__device__ __forceinline__ float tf32r(float x)
{
    unsigned u;
    asm("cvt.rna.tf32.f32 %0, %1;" : "=r"(u) : "f"(x));
    return __uint_as_float(u);
}

// weight pre-convert into packed-B tf32 chunks
__global__ void __launch_bounds__(256) wconv_kernel(
    int layer,
    const float* __restrict__ wqkv, const float* __restrict__ wo,
    const float* __restrict__ wffa, const float* __restrict__ wffb)
{
    int idx = blockIdx.x * 256 + threadIdx.x;
    if (idx >= 12 * CHP) return;
    int cid = idx >> 12;
    int rem = idx & 4095;
    int r = rem >> 6, n = rem & 63;
    float v;
    if (cid < 3)       v = wqkv[r * 192 + 64 * cid + n];
    else if (cid == 3) v = wo[r * 64 + n];
    else if (cid < 8)  v = wffa[r * 256 + 64 * (cid - 4) + n];
    else               v = wffb[(64 * (cid - 8) + r) * 64 + n];
    g_wtf[layer][cid * CHP + pb_idx(r, n)] = tf32r(v);
}

// m16n8k8 tf32 mma. A: a0=(g,t) a1=(g+8,t) a2=(g,t+4) a3=(g+8,t+4);
// B: b0=(k t, col g) b1=(k t+4, col g); D as k4. (g=lane>>2, t=lane&3)
__device__ __forceinline__ void mma8(float4& d, const float* a, float b0, float b1)
{
    asm volatile("mma.sync.aligned.m16n8k8.row.col.f32.tf32.tf32.f32 "
                 "{%0,%1,%2,%3}, {%4,%5,%6,%7}, {%8,%9}, {%0,%1,%2,%3};"
                 : "+f"(d.x), "+f"(d.y), "+f"(d.z), "+f"(d.w)
                 : "r"(__float_as_uint(a[0])), "r"(__float_as_uint(a[1])),
                   "r"(__float_as_uint(a[2])), "r"(__float_as_uint(a[3])),
                   "r"(__float_as_uint(b0)), "r"(__float_as_uint(b1)));
}

// A-fragments for K=64 (8 k8-steps)
__device__ __forceinline__ void load_afrag8(const float* A, int stride, int mrow,
                                            int gid, int tig, float a[8][4])
{
#pragma unroll
    for (int j = 0; j < 8; j++) {
        a[j][0] = A[(mrow + gid) * stride + 8 * j + tig];
        a[j][1] = A[(mrow + gid + 8) * stride + 8 * j + tig];
        a[j][2] = A[(mrow + gid) * stride + 8 * j + tig + 4];
        a[j][3] = A[(mrow + gid + 8) * stride + 8 * j + tig + 4];
    }
}

// 64-K GEMM vs packed-B chunk, one 8-col block cb. Conflict-free: float4
// index within block == lane id.
__device__ __forceinline__ void gemm64(const float a[8][4], const float* pb,
                                       int cb, int tig, int gid, float4& acc)
{
    const float4* pb4 = (const float4*)pb;
#pragma unroll
    for (int j2 = 0; j2 < 4; j2++) {
        float4 b = pb4[(cb * 4 + j2) * 32 + gid * 4 + tig];
        mma8(acc, a[2 * j2],     b.x, b.y);
        mma8(acc, a[2 * j2 + 1], b.z, b.w);
    }
}

__device__ __forceinline__ float gelu_tanh(float x)
{
    float x3 = x * x * x;
    float t = tanhf(0.7978845608028654f * (x + 0.044715f * x3));
    return 0.5f * x * (1.0f + t);
}

// layernorm rows: sx[64][SXS] -> tf32 sxn[64][PAD]  (8 warps x 8 rows)
__device__ __forceinline__ void ln_rows(const float* sx, float* sxn, int tid)
{
    int lane = tid & 31, w = tid >> 5;
#pragma unroll
    for (int rr = 0; rr < 8; rr++) {
        int r = w * 8 + rr;
        float a = sx[r * SXS + lane];
        float b = sx[r * SXS + lane + 32];
        float s = a + b, q = a * a + b * b;
#pragma unroll
        for (int m = 16; m; m >>= 1) {
            s += __shfl_xor_sync(0xffffffffu, s, m);
            q += __shfl_xor_sync(0xffffffffu, q, m);
        }
        float mean = s * (1.0f / 64.0f);
        float rs = rsqrtf(q * (1.0f / 64.0f) - mean * mean + 1e-5f);
        sxn[r * PAD + lane]      = tf32r((a - mean) * rs);
        sxn[r * PAD + lane + 32] = tf32r((b - mean) * rs);
    }
}

// smem: sx 64*66 | sxn 64*68 | pkT 4096 | pv 4096 | satt 128*68
#define SMEM_FLOATS (64*SXS + 64*PAD + CHP + CHP + 128*PAD)
#define SMEM_BYTES  (SMEM_FLOATS * 4)   // 101888 B -> 2 blocks/SM

__global__ void __launch_bounds__(256, 2) layer_kernel(
    int layer,
    const float* __restrict__ feats_in, const float* __restrict__ pts,
    const float* __restrict__ wpos, float* __restrict__ dst_out)
{
    extern __shared__ float smf[];
    float* sx   = smf;                  // [64][66] fp32 residual
    float* sxn  = sx   + 64 * SXS;      // [64][68] ln-out / q / o / ln2 (A-layout)
    float* pkT  = sxn  + 64 * PAD;      // packed B: k (d=dim, col=key) / ffa weights
    float* pv   = pkT  + CHP;           // packed B: v (d=key, col=vd) / ffb weights
    float* satt = pv   + CHP;           // [128][68] att / weight staging / sh
    float* sh   = satt;

    const float* wtf   = g_wtf[layer];
    const float* feats = layer ? g_x1   : feats_in;
    float*       dst   = layer ? dst_out : g_x1;
    const int*   gIdx  = layer ? g_ind12 : g_ind1;
    const int*   pIdx  = layer ? g_ind2  : g_ind1;

    int tid = threadIdx.x;
    int g = blockIdx.x;
    int lane = tid & 31, w = tid >> 5;
    int gid = lane >> 2, tig = lane & 3;
    int mrow = 16 * (w & 3), wsel = w >> 2;   // GEMM map: 4 M-tiles x 2 col-phases
    int hh2 = w & 1, mr2 = 16 * (w >> 1);     // attention map: 2 heads x 4 M-tiles

    float a[8][4];

    // ---- P0: stage wpos (satt); x = feats[gIdx] + p @ wpos ----
    satt[tid] = wpos[tid];
    __syncthreads();
    {
        int r = tid >> 2;
        int cs = (tid & 3) * 16;
        int gi = gIdx[g * GS + r];
        int pi = pIdx[g * GS + r];
        float4 p = *(const float4*)(pts + (size_t)pi * 4);
#pragma unroll
        for (int cc = 0; cc < 16; cc += 4) {
            int c = cs + cc;
            float4 f  = *(const float4*)(feats + (size_t)gi * 64 + c);
            float4 w0 = *(const float4*)(satt + c);
            float4 w1 = *(const float4*)(satt + 64 + c);
            float4 w2 = *(const float4*)(satt + 128 + c);
            float4 w3 = *(const float4*)(satt + 192 + c);
            f.x += p.x * w0.x + p.y * w1.x + p.z * w2.x + p.w * w3.x;
            f.y += p.x * w0.y + p.y * w1.y + p.z * w2.y + p.w * w3.y;
            f.z += p.x * w0.z + p.y * w1.z + p.z * w2.z + p.w * w3.z;
            f.w += p.x * w0.w + p.y * w1.w + p.z * w2.w + p.w * w3.w;
            *(float2*)(sx + r * SXS + c)     = make_float2(f.x, f.y);
            *(float2*)(sx + r * SXS + c + 2) = make_float2(f.z, f.w);
        }
    }
    __syncthreads();

    // ---- P1: ln -> sxn ----
    ln_rows(sx, sxn, tid);
    __syncthreads();

    // ---- P2: q/k/v GEMMs ----
    load_afrag8(sxn, PAD, mrow, gid, tig, a);   // ln frags persist across s
#pragma unroll 1
    for (int s = 0; s < 3; s++) {
        const float4* ws = (const float4*)(wtf + s * CHP);
        for (int i = tid; i < 1024; i += 256) ((float4*)satt)[i] = ws[i];
        __syncthreads();
        float4 acc[4];
#pragma unroll
        for (int u = 0; u < 4; u++) {
            acc[u] = make_float4(0.f, 0.f, 0.f, 0.f);
            gemm64(a, satt, wsel + 2 * u, tig, gid, acc[u]);
        }
#pragma unroll
        for (int u = 0; u < 4; u++) {
            int n0 = 8 * (wsel + 2 * u) + 2 * tig, r0 = mrow + gid;
            if (s == 0) {          // q row-major into sxn
                sxn[r0 * PAD + n0]           = tf32r(acc[u].x);
                sxn[r0 * PAD + n0 + 1]       = tf32r(acc[u].y);
                sxn[(r0 + 8) * PAD + n0]     = tf32r(acc[u].z);
                sxn[(r0 + 8) * PAD + n0 + 1] = tf32r(acc[u].w);
            } else if (s == 1) {   // k packed: d=dim(n0), col=key(r0)
                pkT[pb_idx(n0, r0)]         = tf32r(acc[u].x);
                pkT[pb_idx(n0 + 1, r0)]     = tf32r(acc[u].y);
                pkT[pb_idx(n0, r0 + 8)]     = tf32r(acc[u].z);
                pkT[pb_idx(n0 + 1, r0 + 8)] = tf32r(acc[u].w);
            } else {               // v packed: d=key(r0), col=vd(n0)
                pv[pb_idx(r0, n0)]          = tf32r(acc[u].x);
                pv[pb_idx(r0, n0 + 1)]      = tf32r(acc[u].y);
                pv[pb_idx(r0 + 8, n0)]      = tf32r(acc[u].z);
                pv[pb_idx(r0 + 8, n0 + 1)]  = tf32r(acc[u].w);
            }
        }
        __syncthreads();
    }

    // ---- P3: attention (scores + in-register softmax, then AV) ----
#pragma unroll 1
    for (int p = 0; p < 2; p++) {
        int h = 2 * p + hh2;
        float qa[2][4];
#pragma unroll
        for (int j = 0; j < 2; j++) {
            qa[j][0] = sxn[(mr2 + gid) * PAD + 16 * h + 8 * j + tig];
            qa[j][1] = sxn[(mr2 + gid + 8) * PAD + 16 * h + 8 * j + tig];
            qa[j][2] = sxn[(mr2 + gid) * PAD + 16 * h + 8 * j + tig + 4];
            qa[j][3] = sxn[(mr2 + gid + 8) * PAD + 16 * h + 8 * j + tig + 4];
        }
        float4 sc[8];
        const float4* pk4 = (const float4*)pkT;
#pragma unroll
        for (int u = 0; u < 8; u++) {
            sc[u] = make_float4(0.f, 0.f, 0.f, 0.f);
            float4 b = pk4[(u * 4 + h) * 32 + gid * 4 + tig];  // d-block j2=h
            mma8(sc[u], qa[0], b.x, b.y);
            mma8(sc[u], qa[1], b.z, b.w);
        }
        float s0 = 0.0f, s1 = 0.0f;
#pragma unroll
        for (int u = 0; u < 8; u++) {
            sc[u].x = __expf(sc[u].x * 0.25f);  // 1/sqrt(16); scores O(1), no max
            sc[u].y = __expf(sc[u].y * 0.25f);
            sc[u].z = __expf(sc[u].z * 0.25f);
            sc[u].w = __expf(sc[u].w * 0.25f);
            s0 += sc[u].x + sc[u].y;
            s1 += sc[u].z + sc[u].w;
        }
        s0 += __shfl_xor_sync(0xffffffffu, s0, 1);
        s0 += __shfl_xor_sync(0xffffffffu, s0, 2);
        s1 += __shfl_xor_sync(0xffffffffu, s1, 1);
        s1 += __shfl_xor_sync(0xffffffffu, s1, 2);
        float i0 = 1.0f / s0, i1 = 1.0f / s1;
        int ar = hh2 * 64 + mr2 + gid;
#pragma unroll
        for (int u = 0; u < 8; u++) {
            int n0 = 8 * u + 2 * tig;
            satt[ar * PAD + n0]           = tf32r(sc[u].x * i0);
            satt[ar * PAD + n0 + 1]       = tf32r(sc[u].y * i0);
            satt[(ar + 8) * PAD + n0]     = tf32r(sc[u].z * i1);
            satt[(ar + 8) * PAD + n0 + 1] = tf32r(sc[u].w * i1);
        }
        __syncthreads();
        // AV: o = att @ v -> sxn cols [16h, 16h+16)
        load_afrag8(satt + hh2 * 64 * PAD, PAD, mr2, gid, tig, a);
#pragma unroll
        for (int u = 0; u < 2; u++) {
            float4 acc = make_float4(0.f, 0.f, 0.f, 0.f);
            gemm64(a, pv, 2 * h + u, tig, gid, acc);
            int r0 = mr2 + gid, n0 = 16 * h + 8 * u + 2 * tig;
            sxn[r0 * PAD + n0]           = tf32r(acc.x);
            sxn[r0 * PAD + n0 + 1]       = tf32r(acc.y);
            sxn[(r0 + 8) * PAD + n0]     = tf32r(acc.z);
            sxn[(r0 + 8) * PAD + n0 + 1] = tf32r(acc.w);
        }
        __syncthreads();
    }

    // ---- P3c: x += o @ wo; pre-stage ffa0 (pkT) + ffb0 (pv) ----
    load_afrag8(sxn, PAD, mrow, gid, tig, a);   // o frags
    {
        const float4* wo4 = (const float4*)(wtf + 3 * CHP);
        const float4* fa4 = (const float4*)(wtf + 4 * CHP);
        const float4* fb4 = (const float4*)(wtf + 8 * CHP);
        for (int i = tid; i < 1024; i += 256) {
            ((float4*)satt)[i] = wo4[i];
            ((float4*)pkT)[i]  = fa4[i];
            ((float4*)pv)[i]   = fb4[i];
        }
    }
    __syncthreads();
    {
        float4 acc[4];
#pragma unroll
        for (int u = 0; u < 4; u++) {
            acc[u] = make_float4(0.f, 0.f, 0.f, 0.f);
            gemm64(a, satt, wsel + 2 * u, tig, gid, acc[u]);
        }
#pragma unroll
        for (int u = 0; u < 4; u++) {
            int n0 = 8 * (wsel + 2 * u) + 2 * tig, r0 = mrow + gid;
            sx[r0 * SXS + n0]           += acc[u].x;
            sx[r0 * SXS + n0 + 1]       += acc[u].y;
            sx[(r0 + 8) * SXS + n0]     += acc[u].z;
            sx[(r0 + 8) * SXS + n0 + 1] += acc[u].w;
        }
    }
    __syncthreads();

    // ---- P4: FF, 4 quarters, 2-phase pipeline ----
    ln_rows(sx, sxn, tid);
    __syncthreads();
    float4 accB[4];
#pragma unroll
    for (int u = 0; u < 4; u++) accB[u] = make_float4(0.f, 0.f, 0.f, 0.f);

#pragma unroll 1
    for (int qtr = 0; qtr < 4; qtr++) {
        // phase A: stage ffb(qtr) [qtr>0] || ffa mma -> gelu -> sh
        if (qtr > 0) {
            const float4* fb4 = (const float4*)(wtf + (8 + qtr) * CHP);
            for (int i = tid; i < 1024; i += 256) ((float4*)pv)[i] = fb4[i];
        }
        load_afrag8(sxn, PAD, mrow, gid, tig, a);
        float4 acc[4];
#pragma unroll
        for (int u = 0; u < 4; u++) {
            acc[u] = make_float4(0.f, 0.f, 0.f, 0.f);
            gemm64(a, pkT, wsel + 2 * u, tig, gid, acc[u]);
        }
#pragma unroll
        for (int u = 0; u < 4; u++) {
            int n0 = 8 * (wsel + 2 * u) + 2 * tig, r0 = mrow + gid;
            sh[r0 * PAD + n0]           = tf32r(gelu_tanh(acc[u].x));
            sh[r0 * PAD + n0 + 1]       = tf32r(gelu_tanh(acc[u].y));
            sh[(r0 + 8) * PAD + n0]     = tf32r(gelu_tanh(acc[u].z));
            sh[(r0 + 8) * PAD + n0 + 1] = tf32r(gelu_tanh(acc[u].w));
        }
        __syncthreads();
        // phase B: stage ffa(qtr+1) [qtr<3] || ffb mma -> accB
        if (qtr < 3) {
            const float4* fa4 = (const float4*)(wtf + (4 + qtr + 1) * CHP);
            for (int i = tid; i < 1024; i += 256) ((float4*)pkT)[i] = fa4[i];
        }
        load_afrag8(sh, PAD, mrow, gid, tig, a);
#pragma unroll
        for (int u = 0; u < 4; u++)
            gemm64(a, pv, wsel + 2 * u, tig, gid, accB[u]);
        __syncthreads();
    }

    // ---- write out: dst = x + ff ----
#pragma unroll
    for (int u = 0; u < 4; u++) {
        int n0 = 8 * (wsel + 2 * u) + 2 * tig, r0 = mrow + gid;
        float2 lo = make_float2(sx[r0 * SXS + n0] + accB[u].x,
                                sx[r0 * SXS + n0 + 1] + accB[u].y);
        float2 hi = make_float2(sx[(r0 + 8) * SXS + n0] + accB[u].z,
                                sx[(r0 + 8) * SXS + n0 + 1] + accB[u].w);
        *(float2*)(dst + (size_t)(g * GS + r0) * 64 + n0)     = lo;
        *(float2*)(dst + (size_t)(g * GS + r0 + 8) * 64 + n0) = hi;
    }
}

// ---------------- launch ----------------
extern "C" void kernel_launch(void* const* d_in, const int* in_sizes, int n_in,
                              void* d_out, int out_size)
{
    const float* vox_feats = (const float*)d_in[0];
    const float* pts_coors = (const float*)d_in[1];
    const int*   vox_coors = (const int*)d_in[2];
    const float* w[10];
    for (int i = 0; i < 10; i++) w[i] = (const float*)d_in[n_in - 10 + i];
    float* out = (float*)d_out;

    cudaFuncSetAttribute(layer_kernel, cudaFuncAttributeMaxDynamicSharedMemorySize, SMEM_BYTES);

    codes_kernel<<<N_TOT / 256, 256>>>(vox_coors);
    wconv_kernel<<<(12 * CHP + 255) / 256, 256>>>(0, w[1], w[2], w[3], w[4]);
    wconv_kernel<<<(12 * CHP + 255) / 256, 256>>>(1, w[6], w[7], w[8], w[9]);

    dim3 gl(64, 2);
    bitonic_local_sort<<<gl, 1024>>>();
    for (int k = 8192; k <= N_TOT; k <<= 1) {
        int j = k >> 1;
        while (j >= 4096) {
            if (j >= 8192) {
                bitonic_global2<<<dim3(256, 2), 256>>>(k, j);
                j >>= 2;
            } else {
                bitonic_global<<<dim3(512, 2), 256>>>(k, j);
                j >>= 1;
            }
        }
        bitonic_local_merge<<<gl, 1024>>>(k);
    }

    extract_kernel<<<N_TOT / 256, 256>>>();
    ind12_kernel<<<N_TOT / 256, 256>>>();

    layer_kernel<<<NGRP, 256, SMEM_BYTES>>>(0, vox_feats, pts_coors, w[0], out);
    layer_kernel<<<NGRP, 256, SMEM_BYTES>>>(1, vox_feats, pts_coors, w[5], out);
}

// round 15
// speedup vs baseline: 1.5473x; 1.0284x over previous
#include <cuda_runtime.h>
#include <cuda_bf16.h>
#include <math.h>

typedef unsigned long long ull;

#define N_TOT 262144
#define GS    64
#define NGRP  (N_TOT / GS)

#define PAD 68    // sxn / satt / sh stride (A-frag friendly)
#define SXS 66    // sx stride (float2-only access)
#define CHP 4096  // packed B chunk: 64k x 64col

// ---------------- device scratch (no allocations allowed) ----------------
__device__ ull   g_keys[2][N_TOT];
__device__ int   g_ind1[N_TOT];
__device__ int   g_ind2[N_TOT];
__device__ int   g_inv1[N_TOT];
__device__ int   g_ind12[N_TOT];
__device__ float g_x1[(size_t)N_TOT * 64];
// tf32 packed weights, 12 chunks per layer: 0-2 qkv, 3 wo, 4-7 ffa, 8-11 ffb
__device__ float g_wtf[2][12 * CHP];

// packed-B layout for m16n8k8, conflict-free: within block ((col>>3)*4 + (d>>4)),
// float4 index == consumer lane id ((col&7)*4 + (d&3)); components d+{0,4,8,12}.
__device__ __forceinline__ int pb_idx(int d, int col)
{
    return ((col >> 3) * 4 + (d >> 4)) * 128 + ((col & 7) * 4 + (d & 3)) * 4
         + 2 * ((d >> 3) & 1) + ((d >> 2) & 1);
}

// ---------------- Hilbert encode (Skilling), order = 10 ----------------
__device__ __forceinline__ unsigned hilbert3(unsigned X0, unsigned X1, unsigned X2)
{
    const int order = 10;
    for (unsigned Q = 1u << (order - 1); Q > 1; Q >>= 1) {
        unsigned P = Q - 1;
        if (X0 & Q) X0 ^= P;
        unsigned t = (X0 ^ X1) & P;
        if (X1 & Q) { X0 ^= P; } else { X0 ^= t; X1 ^= t; }
        t = (X0 ^ X2) & P;
        if (X2 & Q) { X0 ^= P; } else { X0 ^= t; X2 ^= t; }
    }
    X1 ^= X0;
    X2 ^= X1;
    unsigned t = 0;
    for (unsigned Q = 1u << (order - 1); Q > 1; Q >>= 1)
        if (X2 & Q) t ^= (Q - 1);
    X0 ^= t; X1 ^= t; X2 ^= t;
    unsigned code = 0;
#pragma unroll
    for (int b = order - 1; b >= 0; b--) {
        code = (code << 3) | (((X0 >> b) & 1u) << 2) | (((X1 >> b) & 1u) << 1) | ((X2 >> b) & 1u);
    }
    return code;
}

__global__ void __launch_bounds__(256) codes_kernel(const int* __restrict__ vox_coors)
{
    int i = blockIdx.x * 256 + threadIdx.x;
    if (i >= N_TOT) return;
    int4 v = ((const int4*)vox_coors)[i];
    unsigned b  = (unsigned)v.x;
    unsigned c1 = hilbert3((unsigned)v.y, (unsigned)v.z,      (unsigned)v.w);
    unsigned c2 = hilbert3((unsigned)v.y, (unsigned)v.z + 1u, (unsigned)v.w + 1u);
    // Reference keys are int32 (JAX x64 off): batch<<30 overflows the sign bit;
    // signed ascending == unsigned ascending of (key ^ 0x80000000).
    unsigned k1 = (((b << 30) | c1) ^ 0x80000000u);
    unsigned k2 = (((b << 30) | c2) ^ 0x80000000u);
    g_keys[0][i] = (((ull)k1) << 32) | (unsigned)i;
    g_keys[1][i] = (((ull)k2) << 32) | (unsigned)i;
}

// ---------------- bitonic sort (uint64 ascending, N = 2^18) ----------------
// full local sort of 8192-element chunks (k <= 8192), 64KB dynamic smem
__global__ void __launch_bounds__(1024) bitonic_local_sort8k()
{
    extern __shared__ ull s[];
    ull* arr = g_keys[blockIdx.y];
    int base = blockIdx.x * 8192;
    int tid = threadIdx.x;
#pragma unroll
    for (int e = 0; e < 8; e++) s[e * 1024 + tid] = arr[base + e * 1024 + tid];
    __syncthreads();
    for (int k = 2; k <= 8192; k <<= 1) {
        for (int j = k >> 1; j >= 1; j >>= 1) {
#pragma unroll
            for (int e = 0; e < 4; e++) {
                int v = e * 1024 + tid;
                int i = ((v & ~(j - 1)) << 1) | (v & (j - 1));
                int l = i | j;
                bool up = (((unsigned)(base + i)) & (unsigned)k) == 0;
                ull A = s[i], B = s[l];
                if ((A > B) == up) { s[i] = B; s[l] = A; }
            }
            __syncthreads();
        }
    }
#pragma unroll
    for (int e = 0; e < 8; e++) arr[base + e * 1024 + tid] = s[e * 1024 + tid];
}

// local merge of 8192-element chunks: j = 4096 .. 1 (k >= 16384)
__global__ void __launch_bounds__(1024) bitonic_local_merge8k(int k)
{
    extern __shared__ ull s[];
    ull* arr = g_keys[blockIdx.y];
    int base = blockIdx.x * 8192;
    int tid = threadIdx.x;
#pragma unroll
    for (int e = 0; e < 8; e++) s[e * 1024 + tid] = arr[base + e * 1024 + tid];
    __syncthreads();
    bool up = (((unsigned)base) & (unsigned)k) == 0;   // constant per chunk
    for (int j = 4096; j >= 1; j >>= 1) {
#pragma unroll
        for (int e = 0; e < 4; e++) {
            int v = e * 1024 + tid;
            int i = ((v & ~(j - 1)) << 1) | (v & (j - 1));
            int l = i | j;
            ull A = s[i], B = s[l];
            if ((A > B) == up) { s[i] = B; s[l] = A; }
        }
        __syncthreads();
    }
#pragma unroll
    for (int e = 0; e < 8; e++) arr[base + e * 1024 + tid] = s[e * 1024 + tid];
}

__global__ void __launch_bounds__(256) bitonic_global(int k, int j)
{
    ull* arr = g_keys[blockIdx.y];
    int v = blockIdx.x * 256 + threadIdx.x;
    int i = ((v & ~(j - 1)) << 1) | (v & (j - 1));
    int l = i | j;
    bool up = (((unsigned)i) & (unsigned)k) == 0;
    ull A = arr[i], B = arr[l];
    if ((A > B) == up) { arr[i] = B; arr[l] = A; }
}

// fused pair of global steps (j, then j/2). Quartet span 2j <= k -> uniform dir.
__global__ void __launch_bounds__(256) bitonic_global2(int k, int j)
{
    ull* arr = g_keys[blockIdx.y];
    int m = j >> 1;
    int v = blockIdx.x * 256 + threadIdx.x;          // 0 .. N/4-1
    int i0 = ((v & ~(m - 1)) << 2) | (v & (m - 1));
    bool up = (((unsigned)i0) & (unsigned)k) == 0;
    ull e0 = arr[i0], e1 = arr[i0 + m], e2 = arr[i0 + 2 * m], e3 = arr[i0 + 3 * m];
    if ((e0 > e2) == up) { ull t = e0; e0 = e2; e2 = t; }
    if ((e1 > e3) == up) { ull t = e1; e1 = e3; e3 = t; }
    if ((e0 > e1) == up) { ull t = e0; e0 = e1; e1 = t; }
    if ((e2 > e3) == up) { ull t = e2; e2 = e3; e3 = t; }
    arr[i0] = e0; arr[i0 + m] = e1; arr[i0 + 2 * m] = e2; arr[i0 + 3 * m] = e3;
}

__global__ void __launch_bounds__(256) extract_kernel()
{
    int i = blockIdx.x * 256 + threadIdx.x;
    int i1 = (int)(g_keys[0][i] & 0xffffffffull);
    int i2 = (int)(g_keys[1][i] & 0xffffffffull);
    g_ind1[i] = i1;
    g_ind2[i] = i2;
    g_inv1[i1] = i;
}

__global__ void __launch_bounds__(256) ind12_kernel()
{
    int i = blockIdx.x * 256 + threadIdx.x;
    g_ind12[i] = g_inv1[g_ind2[i]];
}

// ---------------- tf32 helpers ----------------
__device__ __forceinline__ float tf32r(float x)
{
    unsigned u;
    asm("cvt.rna.tf32.f32 %0, %1;" : "=r"(u) : "f"(x));
    return __uint_as_float(u);
}

// weight pre-convert into packed-B tf32 chunks
__global__ void __launch_bounds__(256) wconv_kernel(
    int layer,
    const float* __restrict__ wqkv, const float* __restrict__ wo,
    const float* __restrict__ wffa, const float* __restrict__ wffb)
{
    int idx = blockIdx.x * 256 + threadIdx.x;
    if (idx >= 12 * CHP) return;
    int cid = idx >> 12;
    int rem = idx & 4095;
    int r = rem >> 6, n = rem & 63;
    float v;
    if (cid < 3)       v = wqkv[r * 192 + 64 * cid + n];
    else if (cid == 3) v = wo[r * 64 + n];
    else if (cid < 8)  v = wffa[r * 256 + 64 * (cid - 4) + n];
    else               v = wffb[(64 * (cid - 8) + r) * 64 + n];
    g_wtf[layer][cid * CHP + pb_idx(r, n)] = tf32r(v);
}

// m16n8k8 tf32 mma. A: a0=(g,t) a1=(g+8,t) a2=(g,t+4) a3=(g+8,t+4);
// B: b0=(k t, col g) b1=(k t+4, col g). (g=lane>>2, t=lane&3)
__device__ __forceinline__ void mma8(float4& d, const float* a, float b0, float b1)
{
    asm volatile("mma.sync.aligned.m16n8k8.row.col.f32.tf32.tf32.f32 "
                 "{%0,%1,%2,%3}, {%4,%5,%6,%7}, {%8,%9}, {%0,%1,%2,%3};"
                 : "+f"(d.x), "+f"(d.y), "+f"(d.z), "+f"(d.w)
                 : "r"(__float_as_uint(a[0])), "r"(__float_as_uint(a[1])),
                   "r"(__float_as_uint(a[2])), "r"(__float_as_uint(a[3])),
                   "r"(__float_as_uint(b0)), "r"(__float_as_uint(b1)));
}

// A-fragments for K=64 (8 k8-steps)
__device__ __forceinline__ void load_afrag8(const float* A, int stride, int mrow,
                                            int gid, int tig, float a[8][4])
{
#pragma unroll
    for (int j = 0; j < 8; j++) {
        a[j][0] = A[(mrow + gid) * stride + 8 * j + tig];
        a[j][1] = A[(mrow + gid + 8) * stride + 8 * j + tig];
        a[j][2] = A[(mrow + gid) * stride + 8 * j + tig + 4];
        a[j][3] = A[(mrow + gid + 8) * stride + 8 * j + tig + 4];
    }
}

// 64-K GEMM vs packed-B chunk, one 8-col block cb (conflict-free LDS.128)
__device__ __forceinline__ void gemm64(const float a[8][4], const float* pb,
                                       int cb, int tig, int gid, float4& acc)
{
    const float4* pb4 = (const float4*)pb;
#pragma unroll
    for (int j2 = 0; j2 < 4; j2++) {
        float4 b = pb4[(cb * 4 + j2) * 32 + gid * 4 + tig];
        mma8(acc, a[2 * j2],     b.x, b.y);
        mma8(acc, a[2 * j2 + 1], b.z, b.w);
    }
}

__device__ __forceinline__ float gelu_tanh(float x)
{
    float u = 0.7978845608028654f * (x + 0.044715f * x * x * x);
    float t;
    asm("tanh.approx.f32 %0, %1;" : "=f"(t) : "f"(u));
    return 0.5f * x * (1.0f + t);
}

// layernorm rows: sx[64][SXS] -> tf32 sxn[64][PAD]  (8 warps x 8 rows)
__device__ __forceinline__ void ln_rows(const float* sx, float* sxn, int tid)
{
    int lane = tid & 31, w = tid >> 5;
#pragma unroll
    for (int rr = 0; rr < 8; rr++) {
        int r = w * 8 + rr;
        float a = sx[r * SXS + lane];
        float b = sx[r * SXS + lane + 32];
        float s = a + b, q = a * a + b * b;
#pragma unroll
        for (int m = 16; m; m >>= 1) {
            s += __shfl_xor_sync(0xffffffffu, s, m);
            q += __shfl_xor_sync(0xffffffffu, q, m);
        }
        float mean = s * (1.0f / 64.0f);
        float rs = rsqrtf(q * (1.0f / 64.0f) - mean * mean + 1e-5f);
        sxn[r * PAD + lane]      = tf32r((a - mean) * rs);
        sxn[r * PAD + lane + 32] = tf32r((b - mean) * rs);
    }
}

// smem: sx 64*66 | sxn 64*68 | pkT 4096 | pv 4096 | satt 128*68
#define SMEM_FLOATS (64*SXS + 64*PAD + CHP + CHP + 128*PAD)
#define SMEM_BYTES  (SMEM_FLOATS * 4)   // 101888 B -> 2 blocks/SM

__global__ void __launch_bounds__(256, 2) layer_kernel(
    int layer,
    const float* __restrict__ feats_in, const float* __restrict__ pts,
    const float* __restrict__ wpos, float* __restrict__ dst_out)
{
    extern __shared__ float smf[];
    float* sx   = smf;                  // [64][66] fp32 residual
    float* sxn  = sx   + 64 * SXS;      // [64][68] ln-out / q / o / ln2 (A-layout)
    float* pkT  = sxn  + 64 * PAD;      // packed B: k (d=dim, col=key) / ffa weights
    float* pv   = pkT  + CHP;           // packed B: v (d=key, col=vd) / ffb weights
    float* satt = pv   + CHP;           // [128][68] att / weight staging / sh
    float* sh   = satt;

    const float* wtf   = g_wtf[layer];
    const float* feats = layer ? g_x1   : feats_in;
    float*       dst   = layer ? dst_out : g_x1;
    const int*   gIdx  = layer ? g_ind12 : g_ind1;
    const int*   pIdx  = layer ? g_ind2  : g_ind1;

    int tid = threadIdx.x;
    int g = blockIdx.x;
    int lane = tid & 31, w = tid >> 5;
    int gid = lane >> 2, tig = lane & 3;
    int mrow = 16 * (w & 3), wsel = w >> 2;   // GEMM map: 4 M-tiles x 2 col-phases
    int hh2 = w & 1, mr2 = 16 * (w >> 1);     // attention map: 2 heads x 4 M-tiles

    float a[8][4];

    // ---- P0: stage wpos (satt); x = feats[gIdx] + p @ wpos ----
    satt[tid] = wpos[tid];
    __syncthreads();
    {
        int r = tid >> 2;
        int cs = (tid & 3) * 16;
        int gi = gIdx[g * GS + r];
        int pi = pIdx[g * GS + r];
        float4 p = *(const float4*)(pts + (size_t)pi * 4);
#pragma unroll
        for (int cc = 0; cc < 16; cc += 4) {
            int c = cs + cc;
            float4 f  = *(const float4*)(feats + (size_t)gi * 64 + c);
            float4 w0 = *(const float4*)(satt + c);
            float4 w1 = *(const float4*)(satt + 64 + c);
            float4 w2 = *(const float4*)(satt + 128 + c);
            float4 w3 = *(const float4*)(satt + 192 + c);
            f.x += p.x * w0.x + p.y * w1.x + p.z * w2.x + p.w * w3.x;
            f.y += p.x * w0.y + p.y * w1.y + p.z * w2.y + p.w * w3.y;
            f.z += p.x * w0.z + p.y * w1.z + p.z * w2.z + p.w * w3.z;
            f.w += p.x * w0.w + p.y * w1.w + p.z * w2.w + p.w * w3.w;
            *(float2*)(sx + r * SXS + c)     = make_float2(f.x, f.y);
            *(float2*)(sx + r * SXS + c + 2) = make_float2(f.z, f.w);
        }
    }
    __syncthreads();

    // ---- P1: ln -> sxn ----
    ln_rows(sx, sxn, tid);
    __syncthreads();

    // ---- P2: q/k/v GEMMs, ONE staging pass (q->satt lo, k->satt hi, v->pv) ----
    load_afrag8(sxn, PAD, mrow, gid, tig, a);   // ln frags (all warps, before bar)
    {
        const float4* wq = (const float4*)(wtf + 0 * CHP);
        const float4* wk = (const float4*)(wtf + 1 * CHP);
        const float4* wv = (const float4*)(wtf + 2 * CHP);
        float4* sq  = (float4*)satt;
        float4* sk  = (float4*)(satt + CHP);    // satt holds 8704 floats >= 8192
        float4* svw = (float4*)pv;
        for (int i = tid; i < 1024; i += 256) {
            sq[i] = wq[i]; sk[i] = wk[i]; svw[i] = wv[i];
        }
    }
    __syncthreads();
    float4 vacc[4];
    {
        float4 acc[4];
        // q -> sxn (row-major; afrags already in regs everywhere)
#pragma unroll
        for (int u = 0; u < 4; u++) {
            acc[u] = make_float4(0.f, 0.f, 0.f, 0.f);
            gemm64(a, satt, wsel + 2 * u, tig, gid, acc[u]);
        }
#pragma unroll
        for (int u = 0; u < 4; u++) {
            int n0 = 8 * (wsel + 2 * u) + 2 * tig, r0 = mrow + gid;
            sxn[r0 * PAD + n0]           = tf32r(acc[u].x);
            sxn[r0 * PAD + n0 + 1]       = tf32r(acc[u].y);
            sxn[(r0 + 8) * PAD + n0]     = tf32r(acc[u].z);
            sxn[(r0 + 8) * PAD + n0 + 1] = tf32r(acc[u].w);
        }
        // k -> pkT packed (d=dim, col=key)
#pragma unroll
        for (int u = 0; u < 4; u++) {
            acc[u] = make_float4(0.f, 0.f, 0.f, 0.f);
            gemm64(a, satt + CHP, wsel + 2 * u, tig, gid, acc[u]);
        }
#pragma unroll
        for (int u = 0; u < 4; u++) {
            int n0 = 8 * (wsel + 2 * u) + 2 * tig, r0 = mrow + gid;
            pkT[pb_idx(n0, r0)]         = tf32r(acc[u].x);
            pkT[pb_idx(n0 + 1, r0)]     = tf32r(acc[u].y);
            pkT[pb_idx(n0, r0 + 8)]     = tf32r(acc[u].z);
            pkT[pb_idx(n0 + 1, r0 + 8)] = tf32r(acc[u].w);
        }
        // v -> registers (pv still holds v weights for other warps)
#pragma unroll
        for (int u = 0; u < 4; u++) {
            vacc[u] = make_float4(0.f, 0.f, 0.f, 0.f);
            gemm64(a, pv, wsel + 2 * u, tig, gid, vacc[u]);
        }
    }
    __syncthreads();   // all v GEMMs done reading pv weights
#pragma unroll
    for (int u = 0; u < 4; u++) {
        int n0 = 8 * (wsel + 2 * u) + 2 * tig, r0 = mrow + gid;
        pv[pb_idx(r0, n0)]         = tf32r(vacc[u].x);
        pv[pb_idx(r0, n0 + 1)]     = tf32r(vacc[u].y);
        pv[pb_idx(r0 + 8, n0)]     = tf32r(vacc[u].z);
        pv[pb_idx(r0 + 8, n0 + 1)] = tf32r(vacc[u].w);
    }
    __syncthreads();   // q,k,v complete

    // ---- P3: attention (scores + in-register softmax, then AV) ----
#pragma unroll 1
    for (int p = 0; p < 2; p++) {
        int h = 2 * p + hh2;
        float qa[2][4];
#pragma unroll
        for (int j = 0; j < 2; j++) {
            qa[j][0] = sxn[(mr2 + gid) * PAD + 16 * h + 8 * j + tig];
            qa[j][1] = sxn[(mr2 + gid + 8) * PAD + 16 * h + 8 * j + tig];
            qa[j][2] = sxn[(mr2 + gid) * PAD + 16 * h + 8 * j + tig + 4];
            qa[j][3] = sxn[(mr2 + gid + 8) * PAD + 16 * h + 8 * j + tig + 4];
        }
        float4 sc[8];
        const float4* pk4 = (const float4*)pkT;
#pragma unroll
        for (int u = 0; u < 8; u++) {
            sc[u] = make_float4(0.f, 0.f, 0.f, 0.f);
            float4 b = pk4[(u * 4 + h) * 32 + gid * 4 + tig];  // d-block j2=h
            mma8(sc[u], qa[0], b.x, b.y);
            mma8(sc[u], qa[1], b.z, b.w);
        }
        float s0 = 0.0f, s1 = 0.0f;
#pragma unroll
        for (int u = 0; u < 8; u++) {
            sc[u].x = __expf(sc[u].x * 0.25f);  // 1/sqrt(16); scores O(1), no max
            sc[u].y = __expf(sc[u].y * 0.25f);
            sc[u].z = __expf(sc[u].z * 0.25f);
            sc[u].w = __expf(sc[u].w * 0.25f);
            s0 += sc[u].x + sc[u].y;
            s1 += sc[u].z + sc[u].w;
        }
        s0 += __shfl_xor_sync(0xffffffffu, s0, 1);
        s0 += __shfl_xor_sync(0xffffffffu, s0, 2);
        s1 += __shfl_xor_sync(0xffffffffu, s1, 1);
        s1 += __shfl_xor_sync(0xffffffffu, s1, 2);
        float i0 = 1.0f / s0, i1 = 1.0f / s1;
        int ar = hh2 * 64 + mr2 + gid;
#pragma unroll
        for (int u = 0; u < 8; u++) {
            int n0 = 8 * u + 2 * tig;
            satt[ar * PAD + n0]           = tf32r(sc[u].x * i0);
            satt[ar * PAD + n0 + 1]       = tf32r(sc[u].y * i0);
            satt[(ar + 8) * PAD + n0]     = tf32r(sc[u].z * i1);
            satt[(ar + 8) * PAD + n0 + 1] = tf32r(sc[u].w * i1);
        }
        __syncthreads();
        // AV: o = att @ v -> sxn cols [16h, 16h+16)
        load_afrag8(satt + hh2 * 64 * PAD, PAD, mr2, gid, tig, a);
#pragma unroll
        for (int u = 0; u < 2; u++) {
            float4 acc = make_float4(0.f, 0.f, 0.f, 0.f);
            gemm64(a, pv, 2 * h + u, tig, gid, acc);
            int r0 = mr2 + gid, n0 = 16 * h + 8 * u + 2 * tig;
            sxn[r0 * PAD + n0]           = tf32r(acc.x);
            sxn[r0 * PAD + n0 + 1]       = tf32r(acc.y);
            sxn[(r0 + 8) * PAD + n0]     = tf32r(acc.z);
            sxn[(r0 + 8) * PAD + n0 + 1] = tf32r(acc.w);
        }
        __syncthreads();
    }

    // ---- P3c: x += o @ wo; pre-stage ffa0 (pkT) + ffb0 (pv) ----
    load_afrag8(sxn, PAD, mrow, gid, tig, a);   // o frags
    {
        const float4* wo4 = (const float4*)(wtf + 3 * CHP);
        const float4* fa4 = (const float4*)(wtf + 4 * CHP);
        const float4* fb4 = (const float4*)(wtf + 8 * CHP);
        for (int i = tid; i < 1024; i += 256) {
            ((float4*)satt)[i] = wo4[i];
            ((float4*)pkT)[i]  = fa4[i];
            ((float4*)pv)[i]   = fb4[i];
        }
    }
    __syncthreads();
    {
        float4 acc[4];
#pragma unroll
        for (int u = 0; u < 4; u++) {
            acc[u] = make_float4(0.f, 0.f, 0.f, 0.f);
            gemm64(a, satt, wsel + 2 * u, tig, gid, acc[u]);
        }
#pragma unroll
        for (int u = 0; u < 4; u++) {
            int n0 = 8 * (wsel + 2 * u) + 2 * tig, r0 = mrow + gid;
            sx[r0 * SXS + n0]           += acc[u].x;
            sx[r0 * SXS + n0 + 1]       += acc[u].y;
            sx[(r0 + 8) * SXS + n0]     += acc[u].z;
            sx[(r0 + 8) * SXS + n0 + 1] += acc[u].w;
        }
    }
    __syncthreads();

    // ---- P4: FF, 4 quarters, 2-phase pipeline ----
    ln_rows(sx, sxn, tid);
    __syncthreads();
    float4 accB[4];
#pragma unroll
    for (int u = 0; u < 4; u++) accB[u] = make_float4(0.f, 0.f, 0.f, 0.f);

#pragma unroll 1
    for (int qtr = 0; qtr < 4; qtr++) {
        // phase A: stage ffb(qtr) [qtr>0] || ffa mma -> gelu -> sh
        if (qtr > 0) {
            const float4* fb4 = (const float4*)(wtf + (8 + qtr) * CHP);
            for (int i = tid; i < 1024; i += 256) ((float4*)pv)[i] = fb4[i];
        }
        load_afrag8(sxn, PAD, mrow, gid, tig, a);
        float4 acc[4];
#pragma unroll
        for (int u = 0; u < 4; u++) {
            acc[u] = make_float4(0.f, 0.f, 0.f, 0.f);
            gemm64(a, pkT, wsel + 2 * u, tig, gid, acc[u]);
        }
#pragma unroll
        for (int u = 0; u < 4; u++) {
            int n0 = 8 * (wsel + 2 * u) + 2 * tig, r0 = mrow + gid;
            sh[r0 * PAD + n0]           = tf32r(gelu_tanh(acc[u].x));
            sh[r0 * PAD + n0 + 1]       = tf32r(gelu_tanh(acc[u].y));
            sh[(r0 + 8) * PAD + n0]     = tf32r(gelu_tanh(acc[u].z));
            sh[(r0 + 8) * PAD + n0 + 1] = tf32r(gelu_tanh(acc[u].w));
        }
        __syncthreads();
        // phase B: stage ffa(qtr+1) [qtr<3] || ffb mma -> accB
        if (qtr < 3) {
            const float4* fa4 = (const float4*)(wtf + (4 + qtr + 1) * CHP);
            for (int i = tid; i < 1024; i += 256) ((float4*)pkT)[i] = fa4[i];
        }
        load_afrag8(sh, PAD, mrow, gid, tig, a);
#pragma unroll
        for (int u = 0; u < 4; u++)
            gemm64(a, pv, wsel + 2 * u, tig, gid, accB[u]);
        __syncthreads();
    }

    // ---- write out: dst = x + ff ----
#pragma unroll
    for (int u = 0; u < 4; u++) {
        int n0 = 8 * (wsel + 2 * u) + 2 * tig, r0 = mrow + gid;
        float2 lo = make_float2(sx[r0 * SXS + n0] + accB[u].x,
                                sx[r0 * SXS + n0 + 1] + accB[u].y);
        float2 hi = make_float2(sx[(r0 + 8) * SXS + n0] + accB[u].z,
                                sx[(r0 + 8) * SXS + n0 + 1] + accB[u].w);
        *(float2*)(dst + (size_t)(g * GS + r0) * 64 + n0)     = lo;
        *(float2*)(dst + (size_t)(g * GS + r0 + 8) * 64 + n0) = hi;
    }
}

// ---------------- launch ----------------
extern "C" void kernel_launch(void* const* d_in, const int* in_sizes, int n_in,
                              void* d_out, int out_size)
{
    const float* vox_feats = (const float*)d_in[0];
    const float* pts_coors = (const float*)d_in[1];
    const int*   vox_coors = (const int*)d_in[2];
    const float* w[10];
    for (int i = 0; i < 10; i++) w[i] = (const float*)d_in[n_in - 10 + i];
    float* out = (float*)d_out;

    cudaFuncSetAttribute(layer_kernel, cudaFuncAttributeMaxDynamicSharedMemorySize, SMEM_BYTES);
    cudaFuncSetAttribute(bitonic_local_sort8k, cudaFuncAttributeMaxDynamicSharedMemorySize, 65536);
    cudaFuncSetAttribute(bitonic_local_merge8k, cudaFuncAttributeMaxDynamicSharedMemorySize, 65536);

    codes_kernel<<<N_TOT / 256, 256>>>(vox_coors);
    wconv_kernel<<<(12 * CHP + 255) / 256, 256>>>(0, w[1], w[2], w[3], w[4]);
    wconv_kernel<<<(12 * CHP + 255) / 256, 256>>>(1, w[6], w[7], w[8], w[9]);

    bitonic_local_sort8k<<<dim3(32, 2), 1024, 65536>>>();
    for (int k = 16384; k <= N_TOT; k <<= 1) {
        int j = k >> 1;
        while (j >= 8192) {
            if (j >= 16384) {
                bitonic_global2<<<dim3(256, 2), 256>>>(k, j);
                j >>= 2;
            } else {
                bitonic_global<<<dim3(512, 2), 256>>>(k, j);
                j >>= 1;
            }
        }
        bitonic_local_merge8k<<<dim3(32, 2), 1024, 65536>>>(k);
    }

    extract_kernel<<<N_TOT / 256, 256>>>();
    ind12_kernel<<<N_TOT / 256, 256>>>();

    layer_kernel<<<NGRP, 256, SMEM_BYTES>>>(0, vox_feats, pts_coors, w[0], out);
    layer_kernel<<<NGRP, 256, SMEM_BYTES>>>(1, vox_feats, pts_coors, w[5], out);
}

// round 17
// speedup vs baseline: 1.6706x; 1.0796x over previous
#include <cuda_runtime.h>
#include <cuda_bf16.h>
#include <math.h>

typedef unsigned long long ull;

#define N_TOT 262144
#define GS    64
#define NGRP  (N_TOT / GS)

#define PAD 68    // sxn / satt / sh stride (A-frag friendly)
#define SXS 66    // sx stride (float2-only access)
#define CHP 4096  // packed B chunk: 64k x 64col

// ---------------- device scratch (no allocations allowed) ----------------
__device__ ull   g_keys[2][N_TOT];
__device__ int   g_ind1[N_TOT];
__device__ int   g_ind2[N_TOT];
__device__ int   g_inv1[N_TOT];
__device__ int   g_ind12[N_TOT];
__device__ float g_x1[(size_t)N_TOT * 64];
// tf32 packed weights, 12 chunks per layer: 0-2 qkv, 3 wo, 4-7 ffa, 8-11 ffb
__device__ float g_wtf[2][12 * CHP];

// packed-B layout for m16n8k8, conflict-free: within block ((col>>3)*4 + (d>>4)),
// float4 index == consumer lane id ((col&7)*4 + (d&3)); components d+{0,4,8,12}.
__device__ __forceinline__ int pb_idx(int d, int col)
{
    return ((col >> 3) * 4 + (d >> 4)) * 128 + ((col & 7) * 4 + (d & 3)) * 4
         + 2 * ((d >> 3) & 1) + ((d >> 2) & 1);
}

// ---------------- Hilbert encode (Skilling), order = 10 ----------------
__device__ __forceinline__ unsigned hilbert3(unsigned X0, unsigned X1, unsigned X2)
{
    const int order = 10;
    for (unsigned Q = 1u << (order - 1); Q > 1; Q >>= 1) {
        unsigned P = Q - 1;
        if (X0 & Q) X0 ^= P;
        unsigned t = (X0 ^ X1) & P;
        if (X1 & Q) { X0 ^= P; } else { X0 ^= t; X1 ^= t; }
        t = (X0 ^ X2) & P;
        if (X2 & Q) { X0 ^= P; } else { X0 ^= t; X2 ^= t; }
    }
    X1 ^= X0;
    X2 ^= X1;
    unsigned t = 0;
    for (unsigned Q = 1u << (order - 1); Q > 1; Q >>= 1)
        if (X2 & Q) t ^= (Q - 1);
    X0 ^= t; X1 ^= t; X2 ^= t;
    unsigned code = 0;
#pragma unroll
    for (int b = order - 1; b >= 0; b--) {
        code = (code << 3) | (((X0 >> b) & 1u) << 2) | (((X1 >> b) & 1u) << 1) | ((X2 >> b) & 1u);
    }
    return code;
}

__global__ void __launch_bounds__(256) codes_kernel(const int* __restrict__ vox_coors)
{
    int i = blockIdx.x * 256 + threadIdx.x;
    if (i >= N_TOT) return;
    int4 v = ((const int4*)vox_coors)[i];
    unsigned b  = (unsigned)v.x;
    unsigned c1 = hilbert3((unsigned)v.y, (unsigned)v.z,      (unsigned)v.w);
    unsigned c2 = hilbert3((unsigned)v.y, (unsigned)v.z + 1u, (unsigned)v.w + 1u);
    // Reference keys are int32 (JAX x64 off): batch<<30 overflows the sign bit;
    // signed ascending == unsigned ascending of (key ^ 0x80000000).
    unsigned k1 = (((b << 30) | c1) ^ 0x80000000u);
    unsigned k2 = (((b << 30) | c2) ^ 0x80000000u);
    g_keys[0][i] = (((ull)k1) << 32) | (unsigned)i;
    g_keys[1][i] = (((ull)k2) << 32) | (unsigned)i;
}

// ---------------- bitonic sort (uint64 ascending, N = 2^18) ----------------
__global__ void __launch_bounds__(1024) bitonic_local_sort()
{
    __shared__ ull s[4096];
    ull* arr = g_keys[blockIdx.y];
    int base = blockIdx.x * 4096;
    int tid = threadIdx.x;
#pragma unroll
    for (int e = 0; e < 4; e++) s[e * 1024 + tid] = arr[base + e * 1024 + tid];
    __syncthreads();
    for (int k = 2; k <= 4096; k <<= 1) {
        for (int j = k >> 1; j >= 1; j >>= 1) {
#pragma unroll
            for (int e = 0; e < 2; e++) {
                int v = e * 1024 + tid;
                int i = ((v & ~(j - 1)) << 1) | (v & (j - 1));
                int l = i | j;
                bool up = (((unsigned)(base + i)) & (unsigned)k) == 0;
                ull A = s[i], B = s[l];
                if ((A > B) == up) { s[i] = B; s[l] = A; }
            }
            __syncthreads();
        }
    }
#pragma unroll
    for (int e = 0; e < 4; e++) arr[base + e * 1024 + tid] = s[e * 1024 + tid];
}

__global__ void __launch_bounds__(1024) bitonic_local_merge(int k)
{
    __shared__ ull s[4096];
    ull* arr = g_keys[blockIdx.y];
    int base = blockIdx.x * 4096;
    int tid = threadIdx.x;
#pragma unroll
    for (int e = 0; e < 4; e++) s[e * 1024 + tid] = arr[base + e * 1024 + tid];
    __syncthreads();
    bool up = (((unsigned)base) & (unsigned)k) == 0;   // constant per chunk
    for (int j = 2048; j >= 1; j >>= 1) {
#pragma unroll
        for (int e = 0; e < 2; e++) {
            int v = e * 1024 + tid;
            int i = ((v & ~(j - 1)) << 1) | (v & (j - 1));
            int l = i | j;
            ull A = s[i], B = s[l];
            if ((A > B) == up) { s[i] = B; s[l] = A; }
        }
        __syncthreads();
    }
#pragma unroll
    for (int e = 0; e < 4; e++) arr[base + e * 1024 + tid] = s[e * 1024 + tid];
}

__global__ void __launch_bounds__(256) bitonic_global(int k, int j)
{
    ull* arr = g_keys[blockIdx.y];
    int v = blockIdx.x * 256 + threadIdx.x;
    int i = ((v & ~(j - 1)) << 1) | (v & (j - 1));
    int l = i | j;
    bool up = (((unsigned)i) & (unsigned)k) == 0;
    ull A = arr[i], B = arr[l];
    if ((A > B) == up) { arr[i] = B; arr[l] = A; }
}

// fused pair of global steps (j, then j/2). Quartet span 2j <= k -> uniform dir.
__global__ void __launch_bounds__(256) bitonic_global2(int k, int j)
{
    ull* arr = g_keys[blockIdx.y];
    int m = j >> 1;
    int v = blockIdx.x * 256 + threadIdx.x;          // 0 .. N/4-1
    int i0 = ((v & ~(m - 1)) << 2) | (v & (m - 1));
    bool up = (((unsigned)i0) & (unsigned)k) == 0;
    ull e0 = arr[i0], e1 = arr[i0 + m], e2 = arr[i0 + 2 * m], e3 = arr[i0 + 3 * m];
    if ((e0 > e2) == up) { ull t = e0; e0 = e2; e2 = t; }
    if ((e1 > e3) == up) { ull t = e1; e1 = e3; e3 = t; }
    if ((e0 > e1) == up) { ull t = e0; e0 = e1; e1 = t; }
    if ((e2 > e3) == up) { ull t = e2; e2 = e3; e3 = t; }
    arr[i0] = e0; arr[i0 + m] = e1; arr[i0 + 2 * m] = e2; arr[i0 + 3 * m] = e3;
}

__global__ void __launch_bounds__(256) extract_kernel()
{
    int i = blockIdx.x * 256 + threadIdx.x;
    int i1 = (int)(g_keys[0][i] & 0xffffffffull);
    int i2 = (int)(g_keys[1][i] & 0xffffffffull);
    g_ind1[i] = i1;
    g_ind2[i] = i2;
    g_inv1[i1] = i;
}

__global__ void __launch_bounds__(256) ind12_kernel()
{
    int i = blockIdx.x * 256 + threadIdx.x;
    g_ind12[i] = g_inv1[g_ind2[i]];
}

// ---------------- tf32 helpers ----------------
__device__ __forceinline__ float tf32r(float x)
{
    unsigned u;
    asm("cvt.rna.tf32.f32 %0, %1;" : "=r"(u) : "f"(x));
    return __uint_as_float(u);
}

// weight pre-convert into packed-B tf32 chunks
__global__ void __launch_bounds__(256) wconv_kernel(
    int layer,
    const float* __restrict__ wqkv, const float* __restrict__ wo,
    const float* __restrict__ wffa, const float* __restrict__ wffb)
{
    int idx = blockIdx.x * 256 + threadIdx.x;
    if (idx >= 12 * CHP) return;
    int cid = idx >> 12;
    int rem = idx & 4095;
    int r = rem >> 6, n = rem & 63;
    float v;
    if (cid < 3)       v = wqkv[r * 192 + 64 * cid + n];
    else if (cid == 3) v = wo[r * 64 + n];
    else if (cid < 8)  v = wffa[r * 256 + 64 * (cid - 4) + n];
    else               v = wffb[(64 * (cid - 8) + r) * 64 + n];
    g_wtf[layer][cid * CHP + pb_idx(r, n)] = tf32r(v);
}

// m16n8k8 tf32 mma. A: a0=(g,t) a1=(g+8,t) a2=(g,t+4) a3=(g+8,t+4);
// B: b0=(k t, col g) b1=(k t+4, col g). (g=lane>>2, t=lane&3)
__device__ __forceinline__ void mma8(float4& d, const float* a, float b0, float b1)
{
    asm volatile("mma.sync.aligned.m16n8k8.row.col.f32.tf32.tf32.f32 "
                 "{%0,%1,%2,%3}, {%4,%5,%6,%7}, {%8,%9}, {%0,%1,%2,%3};"
                 : "+f"(d.x), "+f"(d.y), "+f"(d.z), "+f"(d.w)
                 : "r"(__float_as_uint(a[0])), "r"(__float_as_uint(a[1])),
                   "r"(__float_as_uint(a[2])), "r"(__float_as_uint(a[3])),
                   "r"(__float_as_uint(b0)), "r"(__float_as_uint(b1)));
}

// A-fragments for K=64 (8 k8-steps)
__device__ __forceinline__ void load_afrag8(const float* A, int stride, int mrow,
                                            int gid, int tig, float a[8][4])
{
#pragma unroll
    for (int j = 0; j < 8; j++) {
        a[j][0] = A[(mrow + gid) * stride + 8 * j + tig];
        a[j][1] = A[(mrow + gid + 8) * stride + 8 * j + tig];
        a[j][2] = A[(mrow + gid) * stride + 8 * j + tig + 4];
        a[j][3] = A[(mrow + gid + 8) * stride + 8 * j + tig + 4];
    }
}

// 64-K GEMM vs packed-B chunk, one 8-col block cb (conflict-free LDS.128)
__device__ __forceinline__ void gemm64(const float a[8][4], const float* pb,
                                       int cb, int tig, int gid, float4& acc)
{
    const float4* pb4 = (const float4*)pb;
#pragma unroll
    for (int j2 = 0; j2 < 4; j2++) {
        float4 b = pb4[(cb * 4 + j2) * 32 + gid * 4 + tig];
        mma8(acc, a[2 * j2],     b.x, b.y);
        mma8(acc, a[2 * j2 + 1], b.z, b.w);
    }
}

__device__ __forceinline__ float gelu_tanh(float x)
{
    float u = 0.7978845608028654f * (x + 0.044715f * x * x * x);
    float t;
    asm("tanh.approx.f32 %0, %1;" : "=f"(t) : "f"(u));
    return 0.5f * x * (1.0f + t);
}

// layernorm rows: sx[64][SXS] -> tf32 sxn[64][PAD]  (8 warps x 8 rows)
__device__ __forceinline__ void ln_rows(const float* sx, float* sxn, int tid)
{
    int lane = tid & 31, w = tid >> 5;
#pragma unroll
    for (int rr = 0; rr < 8; rr++) {
        int r = w * 8 + rr;
        float a = sx[r * SXS + lane];
        float b = sx[r * SXS + lane + 32];
        float s = a + b, q = a * a + b * b;
#pragma unroll
        for (int m = 16; m; m >>= 1) {
            s += __shfl_xor_sync(0xffffffffu, s, m);
            q += __shfl_xor_sync(0xffffffffu, q, m);
        }
        float mean = s * (1.0f / 64.0f);
        float rs = rsqrtf(q * (1.0f / 64.0f) - mean * mean + 1e-5f);
        sxn[r * PAD + lane]      = tf32r((a - mean) * rs);
        sxn[r * PAD + lane + 32] = tf32r((b - mean) * rs);
    }
}

// smem: sx 64*66 | sxn 64*68 | pkT 4096 | pv 4096 | satt 128*68
#define SMEM_FLOATS (64*SXS + 64*PAD + CHP + CHP + 128*PAD)
#define SMEM_BYTES  (SMEM_FLOATS * 4)   // 101888 B -> 2 blocks/SM

__global__ void __launch_bounds__(256, 2) layer_kernel(
    int layer,
    const float* __restrict__ feats_in, const float* __restrict__ pts,
    const float* __restrict__ wpos, float* __restrict__ dst_out)
{
    extern __shared__ float smf[];
    float* sx   = smf;                  // [64][66] fp32 residual
    float* sxn  = sx   + 64 * SXS;      // [64][68] ln-out / q / o / ln2 (A-layout)
    float* pkT  = sxn  + 64 * PAD;      // packed B: k (d=dim, col=key) / ffa weights
    float* pv   = pkT  + CHP;           // packed B: v (d=key, col=vd) / ffb weights
    float* satt = pv   + CHP;           // [128][68] att / weight staging / sh
    float* sh   = satt;

    const float* wtf   = g_wtf[layer];
    const float* feats = layer ? g_x1   : feats_in;
    float*       dst   = layer ? dst_out : g_x1;
    const int*   gIdx  = layer ? g_ind12 : g_ind1;
    const int*   pIdx  = layer ? g_ind2  : g_ind1;

    int tid = threadIdx.x;
    int g = blockIdx.x;
    int lane = tid & 31, w = tid >> 5;
    int gid = lane >> 2, tig = lane & 3;
    int mrow = 16 * (w & 3), wsel = w >> 2;   // GEMM map: 4 M-tiles x 2 col-phases
    int hh2 = w & 1, mr2 = 16 * (w >> 1);     // attention map: 2 heads x 4 M-tiles

    float a[8][4];

    // ---- P0: x = feats[gIdx] + p @ wpos (wpos read straight from global/L2) ----
    {
        int r = tid >> 2;
        int cs = (tid & 3) * 16;
        int gi = gIdx[g * GS + r];
        int pi = pIdx[g * GS + r];
        float4 p = *(const float4*)(pts + (size_t)pi * 4);
#pragma unroll
        for (int cc = 0; cc < 16; cc += 4) {
            int c = cs + cc;
            float4 f  = *(const float4*)(feats + (size_t)gi * 64 + c);
            float4 w0 = *(const float4*)(wpos + c);
            float4 w1 = *(const float4*)(wpos + 64 + c);
            float4 w2 = *(const float4*)(wpos + 128 + c);
            float4 w3 = *(const float4*)(wpos + 192 + c);
            f.x += p.x * w0.x + p.y * w1.x + p.z * w2.x + p.w * w3.x;
            f.y += p.x * w0.y + p.y * w1.y + p.z * w2.y + p.w * w3.y;
            f.z += p.x * w0.z + p.y * w1.z + p.z * w2.z + p.w * w3.z;
            f.w += p.x * w0.w + p.y * w1.w + p.z * w2.w + p.w * w3.w;
            *(float2*)(sx + r * SXS + c)     = make_float2(f.x, f.y);
            *(float2*)(sx + r * SXS + c + 2) = make_float2(f.z, f.w);
        }
    }
    __syncthreads();

    // ---- P1: ln -> sxn ----
    ln_rows(sx, sxn, tid);
    __syncthreads();

    // ---- P2: q/k/v GEMMs, ONE staging pass (q->satt lo, k->satt hi, v->pv) ----
    load_afrag8(sxn, PAD, mrow, gid, tig, a);   // ln frags (all warps, before bar)
    {
        const float4* wq = (const float4*)(wtf + 0 * CHP);
        const float4* wk = (const float4*)(wtf + 1 * CHP);
        const float4* wv = (const float4*)(wtf + 2 * CHP);
        float4* sq  = (float4*)satt;
        float4* sk  = (float4*)(satt + CHP);    // satt holds 8704 floats >= 8192
        float4* svw = (float4*)pv;
        for (int i = tid; i < 1024; i += 256) {
            sq[i] = wq[i]; sk[i] = wk[i]; svw[i] = wv[i];
        }
    }
    __syncthreads();
    float4 vacc[4];
    {
        float4 acc[4];
        // q -> sxn (row-major; afrags already in regs everywhere)
#pragma unroll
        for (int u = 0; u < 4; u++) {
            acc[u] = make_float4(0.f, 0.f, 0.f, 0.f);
            gemm64(a, satt, wsel + 2 * u, tig, gid, acc[u]);
        }
#pragma unroll
        for (int u = 0; u < 4; u++) {
            int n0 = 8 * (wsel + 2 * u) + 2 * tig, r0 = mrow + gid;
            sxn[r0 * PAD + n0]           = tf32r(acc[u].x);
            sxn[r0 * PAD + n0 + 1]       = tf32r(acc[u].y);
            sxn[(r0 + 8) * PAD + n0]     = tf32r(acc[u].z);
            sxn[(r0 + 8) * PAD + n0 + 1] = tf32r(acc[u].w);
        }
        // k -> pkT packed (d=dim, col=key)
#pragma unroll
        for (int u = 0; u < 4; u++) {
            acc[u] = make_float4(0.f, 0.f, 0.f, 0.f);
            gemm64(a, satt + CHP, wsel + 2 * u, tig, gid, acc[u]);
        }
#pragma unroll
        for (int u = 0; u < 4; u++) {
            int n0 = 8 * (wsel + 2 * u) + 2 * tig, r0 = mrow + gid;
            pkT[pb_idx(n0, r0)]         = tf32r(acc[u].x);
            pkT[pb_idx(n0 + 1, r0)]     = tf32r(acc[u].y);
            pkT[pb_idx(n0, r0 + 8)]     = tf32r(acc[u].z);
            pkT[pb_idx(n0 + 1, r0 + 8)] = tf32r(acc[u].w);
        }
        // v -> registers (pv still holds v weights for other warps)
#pragma unroll
        for (int u = 0; u < 4; u++) {
            vacc[u] = make_float4(0.f, 0.f, 0.f, 0.f);
            gemm64(a, pv, wsel + 2 * u, tig, gid, vacc[u]);
        }
    }
    __syncthreads();   // all v GEMMs done reading pv weights
#pragma unroll
    for (int u = 0; u < 4; u++) {
        int n0 = 8 * (wsel + 2 * u) + 2 * tig, r0 = mrow + gid;
        pv[pb_idx(r0, n0)]         = tf32r(vacc[u].x);
        pv[pb_idx(r0, n0 + 1)]     = tf32r(vacc[u].y);
        pv[pb_idx(r0 + 8, n0)]     = tf32r(vacc[u].z);
        pv[pb_idx(r0 + 8, n0 + 1)] = tf32r(vacc[u].w);
    }
    __syncthreads();   // q,k,v complete

    // ---- P3: attention. Scores+softmax+AV are WARP-LOCAL (warp (hh2,mr2) writes
    //      and reads only satt rows [hh2*64+mr2, +16)), so passes need only
    //      __syncwarp(); one block barrier at the end before satt is re-staged.
#pragma unroll 1
    for (int p = 0; p < 2; p++) {
        int h = 2 * p + hh2;
        float qa[2][4];
#pragma unroll
        for (int j = 0; j < 2; j++) {
            qa[j][0] = sxn[(mr2 + gid) * PAD + 16 * h + 8 * j + tig];
            qa[j][1] = sxn[(mr2 + gid + 8) * PAD + 16 * h + 8 * j + tig];
            qa[j][2] = sxn[(mr2 + gid) * PAD + 16 * h + 8 * j + tig + 4];
            qa[j][3] = sxn[(mr2 + gid + 8) * PAD + 16 * h + 8 * j + tig + 4];
        }
        float4 sc[8];
        const float4* pk4 = (const float4*)pkT;
#pragma unroll
        for (int u = 0; u < 8; u++) {
            sc[u] = make_float4(0.f, 0.f, 0.f, 0.f);
            float4 b = pk4[(u * 4 + h) * 32 + gid * 4 + tig];  // d-block j2=h
            mma8(sc[u], qa[0], b.x, b.y);
            mma8(sc[u], qa[1], b.z, b.w);
        }
        float s0 = 0.0f, s1 = 0.0f;
#pragma unroll
        for (int u = 0; u < 8; u++) {
            sc[u].x = __expf(sc[u].x * 0.25f);  // 1/sqrt(16); scores O(1), no max
            sc[u].y = __expf(sc[u].y * 0.25f);
            sc[u].z = __expf(sc[u].z * 0.25f);
            sc[u].w = __expf(sc[u].w * 0.25f);
            s0 += sc[u].x + sc[u].y;
            s1 += sc[u].z + sc[u].w;
        }
        s0 += __shfl_xor_sync(0xffffffffu, s0, 1);
        s0 += __shfl_xor_sync(0xffffffffu, s0, 2);
        s1 += __shfl_xor_sync(0xffffffffu, s1, 1);
        s1 += __shfl_xor_sync(0xffffffffu, s1, 2);
        float i0 = 1.0f / s0, i1 = 1.0f / s1;
        int ar = hh2 * 64 + mr2 + gid;
#pragma unroll
        for (int u = 0; u < 8; u++) {
            int n0 = 8 * u + 2 * tig;
            satt[ar * PAD + n0]           = tf32r(sc[u].x * i0);
            satt[ar * PAD + n0 + 1]       = tf32r(sc[u].y * i0);
            satt[(ar + 8) * PAD + n0]     = tf32r(sc[u].z * i1);
            satt[(ar + 8) * PAD + n0 + 1] = tf32r(sc[u].w * i1);
        }
        __syncwarp();
        // AV: o = att @ v -> sxn cols [16h, 16h+16)  (att rows are warp-own)
        load_afrag8(satt + hh2 * 64 * PAD, PAD, mr2, gid, tig, a);
#pragma unroll
        for (int u = 0; u < 2; u++) {
            float4 acc = make_float4(0.f, 0.f, 0.f, 0.f);
            gemm64(a, pv, 2 * h + u, tig, gid, acc);
            int r0 = mr2 + gid, n0 = 16 * h + 8 * u + 2 * tig;
            sxn[r0 * PAD + n0]           = tf32r(acc.x);
            sxn[r0 * PAD + n0 + 1]       = tf32r(acc.y);
            sxn[(r0 + 8) * PAD + n0]     = tf32r(acc.z);
            sxn[(r0 + 8) * PAD + n0 + 1] = tf32r(acc.w);
        }
        __syncwarp();   // own satt reads done before next pass overwrites
    }
    __syncthreads();    // all o written; satt free for re-staging

    // ---- P3c: x += o @ wo; pre-stage ffa0 (pkT) + ffb0 (pv) ----
    load_afrag8(sxn, PAD, mrow, gid, tig, a);   // o frags
    {
        const float4* wo4 = (const float4*)(wtf + 3 * CHP);
        const float4* fa4 = (const float4*)(wtf + 4 * CHP);
        const float4* fb4 = (const float4*)(wtf + 8 * CHP);
        for (int i = tid; i < 1024; i += 256) {
            ((float4*)satt)[i] = wo4[i];
            ((float4*)pkT)[i]  = fa4[i];
            ((float4*)pv)[i]   = fb4[i];
        }
    }
    __syncthreads();
    {
        float4 acc[4];
#pragma unroll
        for (int u = 0; u < 4; u++) {
            acc[u] = make_float4(0.f, 0.f, 0.f, 0.f);
            gemm64(a, satt, wsel + 2 * u, tig, gid, acc[u]);
        }
#pragma unroll
        for (int u = 0; u < 4; u++) {
            int n0 = 8 * (wsel + 2 * u) + 2 * tig, r0 = mrow + gid;
            sx[r0 * SXS + n0]           += acc[u].x;
            sx[r0 * SXS + n0 + 1]       += acc[u].y;
            sx[(r0 + 8) * SXS + n0]     += acc[u].z;
            sx[(r0 + 8) * SXS + n0 + 1] += acc[u].w;
        }
    }
    __syncthreads();

    // ---- P4: FF, 4 quarters, 2-phase pipeline ----
    ln_rows(sx, sxn, tid);
    __syncthreads();
    float4 accB[4];
#pragma unroll
    for (int u = 0; u < 4; u++) accB[u] = make_float4(0.f, 0.f, 0.f, 0.f);

#pragma unroll 1
    for (int qtr = 0; qtr < 4; qtr++) {
        // phase A: stage ffb(qtr) [qtr>0] || ffa mma -> gelu -> sh
        if (qtr > 0) {
            const float4* fb4 = (const float4*)(wtf + (8 + qtr) * CHP);
            for (int i = tid; i < 1024; i += 256) ((float4*)pv)[i] = fb4[i];
        }
        load_afrag8(sxn, PAD, mrow, gid, tig, a);
        float4 acc[4];
#pragma unroll
        for (int u = 0; u < 4; u++) {
            acc[u] = make_float4(0.f, 0.f, 0.f, 0.f);
            gemm64(a, pkT, wsel + 2 * u, tig, gid, acc[u]);
        }
#pragma unroll
        for (int u = 0; u < 4; u++) {
            int n0 = 8 * (wsel + 2 * u) + 2 * tig, r0 = mrow + gid;
            sh[r0 * PAD + n0]           = tf32r(gelu_tanh(acc[u].x));
            sh[r0 * PAD + n0 + 1]       = tf32r(gelu_tanh(acc[u].y));
            sh[(r0 + 8) * PAD + n0]     = tf32r(gelu_tanh(acc[u].z));
            sh[(r0 + 8) * PAD + n0 + 1] = tf32r(gelu_tanh(acc[u].w));
        }
        __syncthreads();
        // phase B: stage ffa(qtr+1) [qtr<3] || ffb mma -> accB
        if (qtr < 3) {
            const float4* fa4 = (const float4*)(wtf + (4 + qtr + 1) * CHP);
            for (int i = tid; i < 1024; i += 256) ((float4*)pkT)[i] = fa4[i];
        }
        load_afrag8(sh, PAD, mrow, gid, tig, a);
#pragma unroll
        for (int u = 0; u < 4; u++)
            gemm64(a, pv, wsel + 2 * u, tig, gid, accB[u]);
        __syncthreads();
    }

    // ---- write out: dst = x + ff ----
#pragma unroll
    for (int u = 0; u < 4; u++) {
        int n0 = 8 * (wsel + 2 * u) + 2 * tig, r0 = mrow + gid;
        float2 lo = make_float2(sx[r0 * SXS + n0] + accB[u].x,
                                sx[r0 * SXS + n0 + 1] + accB[u].y);
        float2 hi = make_float2(sx[(r0 + 8) * SXS + n0] + accB[u].z,
                                sx[(r0 + 8) * SXS + n0 + 1] + accB[u].w);
        *(float2*)(dst + (size_t)(g * GS + r0) * 64 + n0)     = lo;
        *(float2*)(dst + (size_t)(g * GS + r0 + 8) * 64 + n0) = hi;
    }
}

// ---------------- launch ----------------
extern "C" void kernel_launch(void* const* d_in, const int* in_sizes, int n_in,
                              void* d_out, int out_size)
{
    const float* vox_feats = (const float*)d_in[0];
    const float* pts_coors = (const float*)d_in[1];
    const int*   vox_coors = (const int*)d_in[2];
    const float* w[10];
    for (int i = 0; i < 10; i++) w[i] = (const float*)d_in[n_in - 10 + i];
    float* out = (float*)d_out;

    cudaFuncSetAttribute(layer_kernel, cudaFuncAttributeMaxDynamicSharedMemorySize, SMEM_BYTES);

    codes_kernel<<<N_TOT / 256, 256>>>(vox_coors);
    wconv_kernel<<<(12 * CHP + 255) / 256, 256>>>(0, w[1], w[2], w[3], w[4]);
    wconv_kernel<<<(12 * CHP + 255) / 256, 256>>>(1, w[6], w[7], w[8], w[9]);

    dim3 gl(64, 2);
    bitonic_local_sort<<<gl, 1024>>>();
    for (int k = 8192; k <= N_TOT; k <<= 1) {
        int j = k >> 1;
        while (j >= 4096) {
            if (j >= 8192) {
                bitonic_global2<<<dim3(256, 2), 256>>>(k, j);
                j >>= 2;
            } else {
                bitonic_global<<<dim3(512, 2), 256>>>(k, j);
                j >>= 1;
            }
        }
        bitonic_local_merge<<<gl, 1024>>>(k);
    }

    extract_kernel<<<N_TOT / 256, 256>>>();
    ind12_kernel<<<N_TOT / 256, 256>>>();

    layer_kernel<<<NGRP, 256, SMEM_BYTES>>>(0, vox_feats, pts_coors, w[0], out);
    layer_kernel<<<NGRP, 256, SMEM_BYTES>>>(1, vox_feats, pts_coors, w[5], out);
}